// round 2
// baseline (speedup 1.0000x reference)
#include <cuda_runtime.h>
#include <cuda_bf16.h>
#include <mma.h>

using namespace nvcuda;

// ---------------- problem constants ----------------
#define T_LEN   128
#define E_DIM   768
#define H1      128
#define H2      64
#define G1      512   // 4*H1
#define G2      256   // 4*H2
#define NSEQ    920   // 200 support + 200 query + 512 unlabel + 8 model
#define MROWS   (NSEQ * T_LEN)   // 117760
#define SEQ_PER_BLOCK 8
#define LSTM_THREADS  512

// segment row boundaries (rows of the big GEMM)
#define ROW_SUP_END 25600
#define ROW_QRY_END 51200
#define ROW_UNL_END 116736

// ---------------- scratch (device globals; no runtime alloc) ----------------
__device__ float g_xw1[(long)MROWS * G1];   // 241 MB: LSTM1 input projections
__device__ float g_enc[NSEQ * H2];          // final encodings

// ---------------- helpers ----------------
__device__ __forceinline__ float fsig(float x) {
    return 1.0f / (1.0f + __expf(-x));
}
__device__ __forceinline__ float ftanh(float x) {
    x = fminf(12.0f, fmaxf(-12.0f, x));
    float e = __expf(2.0f * x);
    return (e - 1.0f) / (e + 1.0f);
}

// =====================================================================
// Kernel 1: xw1 = X @ W1   (bias added later in the LSTM kernel)
// X is the virtual concat [117760, 768] of support/query/unlabel/model.
// tf32 WMMA, block tile 64x64, K-tile 16, 256 threads (8 warps: 4M x 2N).
// =====================================================================
__global__ __launch_bounds__(256) void gemm1_kernel(
    const float* __restrict__ support,
    const float* __restrict__ query,
    const float* __restrict__ unlabel,
    const float* __restrict__ model,
    const float* __restrict__ W1)
{
    __shared__ float As[64 * 16];
    __shared__ float Bs[16 * 64];

    const int bn = blockIdx.x;        // 0..7   (N tiles of 64)
    const int bm = blockIdx.y;        // 0..1839 (M tiles of 64)
    const long row0 = (long)bm * 64;

    // segment select (boundaries are multiples of 64)
    const float* A;
    long arow;
    if (row0 < ROW_SUP_END)      { A = support; arow = row0; }
    else if (row0 < ROW_QRY_END) { A = query;   arow = row0 - ROW_SUP_END; }
    else if (row0 < ROW_UNL_END) { A = unlabel; arow = row0 - ROW_QRY_END; }
    else                         { A = model;   arow = row0 - ROW_UNL_END; }

    const int tid  = threadIdx.x;
    const int warp = tid >> 5;
    const int wm   = warp & 3;    // 0..3 (16-row slice)
    const int wn   = warp >> 2;   // 0..1 (32-col slice)

    wmma::fragment<wmma::accumulator, 16, 16, 8, float> cf[2];
    wmma::fill_fragment(cf[0], 0.0f);
    wmma::fill_fragment(cf[1], 0.0f);

    // load mappings (float4 granularity)
    const int ar = tid >> 2, ac4 = tid & 3;     // A: 64 rows x 4 float4
    const int br = tid >> 4, bc4 = tid & 15;    // B: 16 rows x 16 float4

    for (int k0 = 0; k0 < E_DIM; k0 += 16) {
        float4 av = *(const float4*)&A[(arow + ar) * E_DIM + k0 + ac4 * 4];
        float4 bv = *(const float4*)&W1[(long)(k0 + br) * G1 + bn * 64 + bc4 * 4];
        *(float4*)&As[ar * 16 + ac4 * 4] = av;
        *(float4*)&Bs[br * 64 + bc4 * 4] = bv;
        __syncthreads();

        #pragma unroll
        for (int kk = 0; kk < 2; kk++) {
            wmma::fragment<wmma::matrix_a, 16, 16, 8, wmma::precision::tf32, wmma::row_major> af;
            wmma::load_matrix_sync(af, &As[(wm * 16) * 16 + kk * 8], 16);
            #pragma unroll
            for (int i = 0; i < af.num_elements; i++)
                af.x[i] = wmma::__float_to_tf32(af.x[i]);
            #pragma unroll
            for (int nn = 0; nn < 2; nn++) {
                wmma::fragment<wmma::matrix_b, 16, 16, 8, wmma::precision::tf32, wmma::row_major> bf;
                wmma::load_matrix_sync(bf, &Bs[(kk * 8) * 64 + wn * 32 + nn * 16], 64);
                #pragma unroll
                for (int i = 0; i < bf.num_elements; i++)
                    bf.x[i] = wmma::__float_to_tf32(bf.x[i]);
                wmma::mma_sync(cf[nn], af, bf, cf[nn]);
            }
        }
        __syncthreads();
    }

    #pragma unroll
    for (int nn = 0; nn < 2; nn++) {
        float* dst = &g_xw1[(row0 + wm * 16) * (long)G1 + bn * 64 + wn * 32 + nn * 16];
        wmma::store_matrix_sync(dst, cf[nn], G1, wmma::mem_row_major);
    }
}

// =====================================================================
// Kernel 2: fused LSTM1 + LSTM2 recurrence. One block = 8 sequences.
// 115 blocks x 512 threads. W2/U2/biases in smem (fp32); U1 streamed
// from L2 (resident, shared across all blocks). Cell states live in
// registers (fixed thread->state mapping each step).
// smem layout (floats):
//   sW2   [0      .. 32767]   128x256
//   sU2   [32768  .. 49151]   64x256
//   zbuf  [49152  .. 53247]   8x512 gate staging (reused as 8x256 for LSTM2)
//   h1T   [53248  .. 54271]   [k=128][s=8]
//   h2T   [54272  .. 54783]   [k=64][s=8]
//   sb1   [54784  .. 55295]
//   sb2   [55296  .. 55551]
// total = 55552 floats = 222208 bytes
// =====================================================================
#define LSTM_SMEM_FLOATS 55552
#define LSTM_SMEM_BYTES  (LSTM_SMEM_FLOATS * 4)

__global__ __launch_bounds__(LSTM_THREADS) void lstm_kernel(
    const float* __restrict__ U1,
    const float* __restrict__ b1,
    const float* __restrict__ W2,
    const float* __restrict__ U2,
    const float* __restrict__ b2)
{
    extern __shared__ float sm[];
    float* sW2  = sm;
    float* sU2  = sm + 32768;
    float* zbuf = sm + 49152;
    float* h1T  = sm + 53248;
    float* h2T  = sm + 54272;
    float* sb1  = sm + 54784;
    float* sb2  = sm + 55296;

    const int tid = threadIdx.x;
    const long qbase = (long)blockIdx.x * SEQ_PER_BLOCK;

    // ---- preload weights & init state ----
    {
        const float4* s4 = (const float4*)W2;
        float4* d4 = (float4*)sW2;
        for (int i = tid; i < (H1 * G2) / 4; i += LSTM_THREADS) d4[i] = s4[i];
        s4 = (const float4*)U2; d4 = (float4*)sU2;
        for (int i = tid; i < (H2 * G2) / 4; i += LSTM_THREADS) d4[i] = s4[i];
        sb1[tid] = b1[tid];
        if (tid < G2) sb2[tid] = b2[tid];
        for (int i = tid; i < 128 * 8; i += LSTM_THREADS) h1T[i] = 0.0f;
        if (tid < 64 * 8) h2T[tid] = 0.0f;
    }
    __syncthreads();

    float c1a = 0.0f, c1b = 0.0f, c2 = 0.0f;

    const int j = tid;               // gate column for LSTM1 (0..511)
    const int j2 = tid & 255;        // gate column for LSTM2
    const int s0 = (tid >> 8) * 4;   // sequence half for LSTM2 matvec

    // fixed thread->state mappings
    const int p0s = tid >> 7, p0n = tid & 127;      // LSTM1 pair 0: s=0..3
    const int p1s = 4 + (tid >> 7), p1n = tid & 127; // LSTM1 pair 1: s=4..7
    const int u2s = tid >> 6, u2n = tid & 63;        // LSTM2 state

    for (int t = 0; t < T_LEN; t++) {
        // ---------- Phase A: z1 = xw1_t + b1 + h1 @ U1 ----------
        float acc[8];
        #pragma unroll
        for (int s = 0; s < 8; s++)
            acc[s] = g_xw1[((qbase + s) * T_LEN + t) * (long)G1 + j] + sb1[j];

        #pragma unroll 4
        for (int k = 0; k < H1; k++) {
            float4 ha = *(const float4*)&h1T[k * 8];
            float4 hb = *(const float4*)&h1T[k * 8 + 4];
            float u = U1[k * G1 + j];
            acc[0] = fmaf(ha.x, u, acc[0]);
            acc[1] = fmaf(ha.y, u, acc[1]);
            acc[2] = fmaf(ha.z, u, acc[2]);
            acc[3] = fmaf(ha.w, u, acc[3]);
            acc[4] = fmaf(hb.x, u, acc[4]);
            acc[5] = fmaf(hb.y, u, acc[5]);
            acc[6] = fmaf(hb.z, u, acc[6]);
            acc[7] = fmaf(hb.w, u, acc[7]);
        }
        #pragma unroll
        for (int s = 0; s < 8; s++) zbuf[s * G1 + j] = acc[s];
        __syncthreads();

        // ---------- LSTM1 cell/hidden update (2 states per thread) ----------
        {
            const float* zb = &zbuf[p0s * G1];
            float zi = zb[p0n], zf = zb[128 + p0n], zg = zb[256 + p0n], zo = zb[384 + p0n];
            c1a = fsig(zf) * c1a + fsig(zi) * ftanh(zg);
            h1T[p0n * 8 + p0s] = fsig(zo) * ftanh(c1a);
        }
        {
            const float* zb = &zbuf[p1s * G1];
            float zi = zb[p1n], zf = zb[128 + p1n], zg = zb[256 + p1n], zo = zb[384 + p1n];
            c1b = fsig(zf) * c1b + fsig(zi) * ftanh(zg);
            h1T[p1n * 8 + p1s] = fsig(zo) * ftanh(c1b);
        }
        __syncthreads();

        // ---------- Phase B: z2 = b2 + h1 @ W2 + h2 @ U2 ----------
        float acc2[4];
        #pragma unroll
        for (int ss = 0; ss < 4; ss++) acc2[ss] = sb2[j2];

        #pragma unroll 4
        for (int k = 0; k < H1; k++) {
            float4 h4 = *(const float4*)&h1T[k * 8 + s0];
            float w = sW2[k * G2 + j2];
            acc2[0] = fmaf(h4.x, w, acc2[0]);
            acc2[1] = fmaf(h4.y, w, acc2[1]);
            acc2[2] = fmaf(h4.z, w, acc2[2]);
            acc2[3] = fmaf(h4.w, w, acc2[3]);
        }
        #pragma unroll 4
        for (int k = 0; k < H2; k++) {
            float4 h4 = *(const float4*)&h2T[k * 8 + s0];
            float u = sU2[k * G2 + j2];
            acc2[0] = fmaf(h4.x, u, acc2[0]);
            acc2[1] = fmaf(h4.y, u, acc2[1]);
            acc2[2] = fmaf(h4.z, u, acc2[2]);
            acc2[3] = fmaf(h4.w, u, acc2[3]);
        }
        #pragma unroll
        for (int ss = 0; ss < 4; ss++) zbuf[(s0 + ss) * G2 + j2] = acc2[ss];
        __syncthreads();

        // ---------- LSTM2 cell/hidden update (1 state per thread) ----------
        {
            const float* zb = &zbuf[u2s * G2];
            float zi = zb[u2n], zf = zb[64 + u2n], zg = zb[128 + u2n], zo = zb[192 + u2n];
            c2 = fsig(zf) * c2 + fsig(zi) * ftanh(zg);
            h2T[u2n * 8 + u2s] = fsig(zo) * ftanh(c2);
        }
        __syncthreads();
    }

    // write final encodings
    g_enc[(qbase + u2s) * H2 + u2n] = h2T[u2n * 8 + u2s];
}

// =====================================================================
// Kernel 3: head = BN(relu(concat(enc, m_enc) @ W + b))
// one block per output row, 128 threads
// =====================================================================
__global__ __launch_bounds__(128) void head_kernel(
    int encBase, int groupPerBatch,
    const float* __restrict__ W, const float* __restrict__ b,
    const float* __restrict__ g, const float* __restrict__ beta,
    const float* __restrict__ m, const float* __restrict__ v,
    float* __restrict__ out)
{
    __shared__ float x[128];
    const int row = blockIdx.x;
    const int tid = threadIdx.x;
    const int bidx = row / groupPerBatch;

    if (tid < 64) x[tid] = g_enc[(encBase + row) * H2 + tid];
    else          x[tid] = g_enc[(912 + bidx) * H2 + (tid - 64)];
    __syncthreads();

    if (tid < 32) {
        float acc = b[tid];
        #pragma unroll 8
        for (int k = 0; k < 128; k++) acc = fmaf(x[k], W[k * 32 + tid], acc);
        float y = fmaxf(acc, 0.0f);
        out[row * 32 + tid] = g[tid] * (y - m[tid]) * rsqrtf(v[tid] + 1e-3f) + beta[tid];
    }
}

// =====================================================================
extern "C" void kernel_launch(void* const* d_in, const int* in_sizes, int n_in,
                              void* d_out, int out_size)
{
    (void)in_sizes; (void)n_in; (void)out_size;

    const float* support = (const float*)d_in[0];
    const float* query   = (const float*)d_in[1];
    const float* unlabel = (const float*)d_in[2];
    const float* model   = (const float*)d_in[3];
    const float* W1 = (const float*)d_in[4];
    const float* U1 = (const float*)d_in[5];
    const float* b1 = (const float*)d_in[6];
    const float* W2 = (const float*)d_in[7];
    const float* U2 = (const float*)d_in[8];
    const float* b2 = (const float*)d_in[9];
    float* out = (float*)d_out;

    // Phase 1: big input-projection GEMM (tf32 WMMA)
    dim3 ggrid(G1 / 64, MROWS / 64);
    gemm1_kernel<<<ggrid, 256>>>(support, query, unlabel, model, W1);

    // Phase 2: fused 2-layer LSTM recurrence
    cudaFuncSetAttribute(lstm_kernel,
                         cudaFuncAttributeMaxDynamicSharedMemorySize,
                         LSTM_SMEM_BYTES);
    lstm_kernel<<<NSEQ / SEQ_PER_BLOCK, LSTM_THREADS, LSTM_SMEM_BYTES>>>(
        U1, b1, W2, U2, b2);

    // Phase 3: heads (support / query / unlabel)
    head_kernel<<<200, 128>>>(0, 25,
        (const float*)d_in[10], (const float*)d_in[11], (const float*)d_in[12],
        (const float*)d_in[13], (const float*)d_in[14], (const float*)d_in[15],
        out);
    head_kernel<<<200, 128>>>(200, 25,
        (const float*)d_in[16], (const float*)d_in[17], (const float*)d_in[18],
        (const float*)d_in[19], (const float*)d_in[20], (const float*)d_in[21],
        out + 200 * 32);
    head_kernel<<<512, 128>>>(400, 64,
        (const float*)d_in[22], (const float*)d_in[23], (const float*)d_in[24],
        (const float*)d_in[25], (const float*)d_in[26], (const float*)d_in[27],
        out + 400 * 32);
}

// round 3
// speedup vs baseline: 1.0021x; 1.0021x over previous
#include <cuda_runtime.h>
#include <cuda_bf16.h>
#include <mma.h>

using namespace nvcuda;

// ---------------- problem constants ----------------
#define T_LEN   128
#define E_DIM   768
#define H1      128
#define H2      64
#define G1      512   // 4*H1
#define G2      256   // 4*H2
#define NSEQ    920   // 200 support + 200 query + 512 unlabel + 8 model
#define MROWS   (NSEQ * T_LEN)   // 117760
#define SEQ_PER_BLOCK 8
#define LSTM_THREADS  512

// segment row boundaries (rows of the big GEMM)
#define ROW_SUP_END 25600
#define ROW_QRY_END 51200
#define ROW_UNL_END 116736

// ---------------- scratch (device globals; no runtime alloc) ----------------
__device__ float g_xw1[(long)MROWS * G1];   // 241 MB: LSTM1 input projections
__device__ float g_enc[NSEQ * H2];          // final encodings

// ---------------- helpers ----------------
__device__ __forceinline__ float fsig(float x) {
    return 1.0f / (1.0f + __expf(-x));
}
__device__ __forceinline__ float ftanh(float x) {
    x = fminf(12.0f, fmaxf(-12.0f, x));
    float e = __expf(2.0f * x);
    return (e - 1.0f) / (e + 1.0f);
}

// =====================================================================
// Kernel 1: xw1 = X @ W1   (bias added later in the LSTM kernel)
// X is the virtual concat [117760, 768] of support/query/unlabel/model.
// tf32 WMMA, block tile 64x64, K-tile 16, 256 threads (8 warps: 4M x 2N).
// =====================================================================
__global__ __launch_bounds__(256) void gemm1_kernel(
    const float* __restrict__ support,
    const float* __restrict__ query,
    const float* __restrict__ unlabel,
    const float* __restrict__ model,
    const float* __restrict__ W1)
{
    __shared__ float As[64 * 16];
    __shared__ float Bs[16 * 64];

    const int bn = blockIdx.x;        // 0..7   (N tiles of 64)
    const int bm = blockIdx.y;        // 0..1839 (M tiles of 64)
    const long row0 = (long)bm * 64;

    // segment select (boundaries are multiples of 64)
    const float* A;
    long arow;
    if (row0 < ROW_SUP_END)      { A = support; arow = row0; }
    else if (row0 < ROW_QRY_END) { A = query;   arow = row0 - ROW_SUP_END; }
    else if (row0 < ROW_UNL_END) { A = unlabel; arow = row0 - ROW_QRY_END; }
    else                         { A = model;   arow = row0 - ROW_UNL_END; }

    const int tid  = threadIdx.x;
    const int warp = tid >> 5;
    const int wm   = warp & 3;    // 0..3 (16-row slice)
    const int wn   = warp >> 2;   // 0..1 (32-col slice)

    wmma::fragment<wmma::accumulator, 16, 16, 8, float> cf[2];
    wmma::fill_fragment(cf[0], 0.0f);
    wmma::fill_fragment(cf[1], 0.0f);

    // load mappings (float4 granularity)
    const int ar = tid >> 2, ac4 = tid & 3;     // A: 64 rows x 4 float4
    const int br = tid >> 4, bc4 = tid & 15;    // B: 16 rows x 16 float4

    for (int k0 = 0; k0 < E_DIM; k0 += 16) {
        float4 av = *(const float4*)&A[(arow + ar) * E_DIM + k0 + ac4 * 4];
        float4 bv = *(const float4*)&W1[(long)(k0 + br) * G1 + bn * 64 + bc4 * 4];
        *(float4*)&As[ar * 16 + ac4 * 4] = av;
        *(float4*)&Bs[br * 64 + bc4 * 4] = bv;
        __syncthreads();

        #pragma unroll
        for (int kk = 0; kk < 2; kk++) {
            wmma::fragment<wmma::matrix_a, 16, 16, 8, wmma::precision::tf32, wmma::row_major> af;
            wmma::load_matrix_sync(af, &As[(wm * 16) * 16 + kk * 8], 16);
            #pragma unroll
            for (int i = 0; i < af.num_elements; i++)
                af.x[i] = wmma::__float_to_tf32(af.x[i]);
            #pragma unroll
            for (int nn = 0; nn < 2; nn++) {
                wmma::fragment<wmma::matrix_b, 16, 16, 8, wmma::precision::tf32, wmma::row_major> bf;
                wmma::load_matrix_sync(bf, &Bs[(kk * 8) * 64 + wn * 32 + nn * 16], 64);
                #pragma unroll
                for (int i = 0; i < bf.num_elements; i++)
                    bf.x[i] = wmma::__float_to_tf32(bf.x[i]);
                wmma::mma_sync(cf[nn], af, bf, cf[nn]);
            }
        }
        __syncthreads();
    }

    #pragma unroll
    for (int nn = 0; nn < 2; nn++) {
        float* dst = &g_xw1[(row0 + wm * 16) * (long)G1 + bn * 64 + wn * 32 + nn * 16];
        wmma::store_matrix_sync(dst, cf[nn], G1, wmma::mem_row_major);
    }
}

// =====================================================================
// Kernel 2: fused LSTM1 + LSTM2 recurrence. One block = 8 sequences.
// 115 blocks x 512 threads. W2/U2/biases in smem (fp32); U1 streamed
// from L2 (resident, shared across all blocks). Cell states live in
// registers (fixed thread->state mapping each step).
// smem layout (floats):
//   sW2   [0      .. 32767]   128x256
//   sU2   [32768  .. 49151]   64x256
//   zbuf  [49152  .. 53247]   8x512 gate staging (reused as 8x256 for LSTM2)
//   h1T   [53248  .. 54271]   [k=128][s=8]
//   h2T   [54272  .. 54783]   [k=64][s=8]
//   sb1   [54784  .. 55295]
//   sb2   [55296  .. 55551]
// total = 55552 floats = 222208 bytes
// =====================================================================
#define LSTM_SMEM_FLOATS 55552
#define LSTM_SMEM_BYTES  (LSTM_SMEM_FLOATS * 4)

__global__ __launch_bounds__(LSTM_THREADS) void lstm_kernel(
    const float* __restrict__ U1,
    const float* __restrict__ b1,
    const float* __restrict__ W2,
    const float* __restrict__ U2,
    const float* __restrict__ b2)
{
    extern __shared__ float sm[];
    float* sW2  = sm;
    float* sU2  = sm + 32768;
    float* zbuf = sm + 49152;
    float* h1T  = sm + 53248;
    float* h2T  = sm + 54272;
    float* sb1  = sm + 54784;
    float* sb2  = sm + 55296;

    const int tid = threadIdx.x;
    const long qbase = (long)blockIdx.x * SEQ_PER_BLOCK;

    // ---- preload weights & init state ----
    {
        const float4* s4 = (const float4*)W2;
        float4* d4 = (float4*)sW2;
        for (int i = tid; i < (H1 * G2) / 4; i += LSTM_THREADS) d4[i] = s4[i];
        s4 = (const float4*)U2; d4 = (float4*)sU2;
        for (int i = tid; i < (H2 * G2) / 4; i += LSTM_THREADS) d4[i] = s4[i];
        sb1[tid] = b1[tid];
        if (tid < G2) sb2[tid] = b2[tid];
        for (int i = tid; i < 128 * 8; i += LSTM_THREADS) h1T[i] = 0.0f;
        if (tid < 64 * 8) h2T[tid] = 0.0f;
    }
    __syncthreads();

    float c1a = 0.0f, c1b = 0.0f, c2 = 0.0f;

    const int j = tid;               // gate column for LSTM1 (0..511)
    const int j2 = tid & 255;        // gate column for LSTM2
    const int s0 = (tid >> 8) * 4;   // sequence half for LSTM2 matvec

    // fixed thread->state mappings
    const int p0s = tid >> 7, p0n = tid & 127;      // LSTM1 pair 0: s=0..3
    const int p1s = 4 + (tid >> 7), p1n = tid & 127; // LSTM1 pair 1: s=4..7
    const int u2s = tid >> 6, u2n = tid & 63;        // LSTM2 state

    for (int t = 0; t < T_LEN; t++) {
        // ---------- Phase A: z1 = xw1_t + b1 + h1 @ U1 ----------
        float acc[8];
        #pragma unroll
        for (int s = 0; s < 8; s++)
            acc[s] = g_xw1[((qbase + s) * T_LEN + t) * (long)G1 + j] + sb1[j];

        #pragma unroll 4
        for (int k = 0; k < H1; k++) {
            float4 ha = *(const float4*)&h1T[k * 8];
            float4 hb = *(const float4*)&h1T[k * 8 + 4];
            float u = U1[k * G1 + j];
            acc[0] = fmaf(ha.x, u, acc[0]);
            acc[1] = fmaf(ha.y, u, acc[1]);
            acc[2] = fmaf(ha.z, u, acc[2]);
            acc[3] = fmaf(ha.w, u, acc[3]);
            acc[4] = fmaf(hb.x, u, acc[4]);
            acc[5] = fmaf(hb.y, u, acc[5]);
            acc[6] = fmaf(hb.z, u, acc[6]);
            acc[7] = fmaf(hb.w, u, acc[7]);
        }
        #pragma unroll
        for (int s = 0; s < 8; s++) zbuf[s * G1 + j] = acc[s];
        __syncthreads();

        // ---------- LSTM1 cell/hidden update (2 states per thread) ----------
        {
            const float* zb = &zbuf[p0s * G1];
            float zi = zb[p0n], zf = zb[128 + p0n], zg = zb[256 + p0n], zo = zb[384 + p0n];
            c1a = fsig(zf) * c1a + fsig(zi) * ftanh(zg);
            h1T[p0n * 8 + p0s] = fsig(zo) * ftanh(c1a);
        }
        {
            const float* zb = &zbuf[p1s * G1];
            float zi = zb[p1n], zf = zb[128 + p1n], zg = zb[256 + p1n], zo = zb[384 + p1n];
            c1b = fsig(zf) * c1b + fsig(zi) * ftanh(zg);
            h1T[p1n * 8 + p1s] = fsig(zo) * ftanh(c1b);
        }
        __syncthreads();

        // ---------- Phase B: z2 = b2 + h1 @ W2 + h2 @ U2 ----------
        float acc2[4];
        #pragma unroll
        for (int ss = 0; ss < 4; ss++) acc2[ss] = sb2[j2];

        #pragma unroll 4
        for (int k = 0; k < H1; k++) {
            float4 h4 = *(const float4*)&h1T[k * 8 + s0];
            float w = sW2[k * G2 + j2];
            acc2[0] = fmaf(h4.x, w, acc2[0]);
            acc2[1] = fmaf(h4.y, w, acc2[1]);
            acc2[2] = fmaf(h4.z, w, acc2[2]);
            acc2[3] = fmaf(h4.w, w, acc2[3]);
        }
        #pragma unroll 4
        for (int k = 0; k < H2; k++) {
            float4 h4 = *(const float4*)&h2T[k * 8 + s0];
            float u = sU2[k * G2 + j2];
            acc2[0] = fmaf(h4.x, u, acc2[0]);
            acc2[1] = fmaf(h4.y, u, acc2[1]);
            acc2[2] = fmaf(h4.z, u, acc2[2]);
            acc2[3] = fmaf(h4.w, u, acc2[3]);
        }
        #pragma unroll
        for (int ss = 0; ss < 4; ss++) zbuf[(s0 + ss) * G2 + j2] = acc2[ss];
        __syncthreads();

        // ---------- LSTM2 cell/hidden update (1 state per thread) ----------
        {
            const float* zb = &zbuf[u2s * G2];
            float zi = zb[u2n], zf = zb[64 + u2n], zg = zb[128 + u2n], zo = zb[192 + u2n];
            c2 = fsig(zf) * c2 + fsig(zi) * ftanh(zg);
            h2T[u2n * 8 + u2s] = fsig(zo) * ftanh(c2);
        }
        __syncthreads();
    }

    // write final encodings
    g_enc[(qbase + u2s) * H2 + u2n] = h2T[u2n * 8 + u2s];
}

// =====================================================================
// Kernel 3: head = BN(relu(concat(enc, m_enc) @ W + b))
// one block per output row, 128 threads
// =====================================================================
__global__ __launch_bounds__(128) void head_kernel(
    int encBase, int groupPerBatch,
    const float* __restrict__ W, const float* __restrict__ b,
    const float* __restrict__ g, const float* __restrict__ beta,
    const float* __restrict__ m, const float* __restrict__ v,
    float* __restrict__ out)
{
    __shared__ float x[128];
    const int row = blockIdx.x;
    const int tid = threadIdx.x;
    const int bidx = row / groupPerBatch;

    if (tid < 64) x[tid] = g_enc[(encBase + row) * H2 + tid];
    else          x[tid] = g_enc[(912 + bidx) * H2 + (tid - 64)];
    __syncthreads();

    if (tid < 32) {
        float acc = b[tid];
        #pragma unroll 8
        for (int k = 0; k < 128; k++) acc = fmaf(x[k], W[k * 32 + tid], acc);
        float y = fmaxf(acc, 0.0f);
        out[row * 32 + tid] = g[tid] * (y - m[tid]) * rsqrtf(v[tid] + 1e-3f) + beta[tid];
    }
}

// =====================================================================
extern "C" void kernel_launch(void* const* d_in, const int* in_sizes, int n_in,
                              void* d_out, int out_size)
{
    (void)in_sizes; (void)n_in; (void)out_size;

    const float* support = (const float*)d_in[0];
    const float* query   = (const float*)d_in[1];
    const float* unlabel = (const float*)d_in[2];
    const float* model   = (const float*)d_in[3];
    const float* W1 = (const float*)d_in[4];
    const float* U1 = (const float*)d_in[5];
    const float* b1 = (const float*)d_in[6];
    const float* W2 = (const float*)d_in[7];
    const float* U2 = (const float*)d_in[8];
    const float* b2 = (const float*)d_in[9];
    float* out = (float*)d_out;

    // Phase 1: big input-projection GEMM (tf32 WMMA)
    dim3 ggrid(G1 / 64, MROWS / 64);
    gemm1_kernel<<<ggrid, 256>>>(support, query, unlabel, model, W1);

    // Phase 2: fused 2-layer LSTM recurrence
    cudaFuncSetAttribute(lstm_kernel,
                         cudaFuncAttributeMaxDynamicSharedMemorySize,
                         LSTM_SMEM_BYTES);
    lstm_kernel<<<NSEQ / SEQ_PER_BLOCK, LSTM_THREADS, LSTM_SMEM_BYTES>>>(
        U1, b1, W2, U2, b2);

    // Phase 3: heads (support / query / unlabel)
    head_kernel<<<200, 128>>>(0, 25,
        (const float*)d_in[10], (const float*)d_in[11], (const float*)d_in[12],
        (const float*)d_in[13], (const float*)d_in[14], (const float*)d_in[15],
        out);
    head_kernel<<<200, 128>>>(200, 25,
        (const float*)d_in[16], (const float*)d_in[17], (const float*)d_in[18],
        (const float*)d_in[19], (const float*)d_in[20], (const float*)d_in[21],
        out + 200 * 32);
    head_kernel<<<512, 128>>>(400, 64,
        (const float*)d_in[22], (const float*)d_in[23], (const float*)d_in[24],
        (const float*)d_in[25], (const float*)d_in[26], (const float*)d_in[27],
        out + 400 * 32);
}

// round 4
// speedup vs baseline: 1.4963x; 1.4931x over previous
#include <cuda_runtime.h>
#include <cuda_bf16.h>
#include <mma.h>

using namespace nvcuda;

// ---------------- problem constants ----------------
#define T_LEN   128
#define E_DIM   768
#define H1      128
#define H2      64
#define G1      512   // 4*H1
#define G2      256   // 4*H2
#define NSEQ    920
#define MROWS   (NSEQ * T_LEN)   // 117760
#define SEQ_PER_BLOCK 8
#define LSTM_THREADS  512

#define ROW_SUP_END 25600
#define ROW_QRY_END 51200
#define ROW_UNL_END 116736

// ---------------- scratch ----------------
__device__ float g_xw1[(long)MROWS * G1];   // 241 MB
__device__ float g_enc[NSEQ * H2];

// ---------------- helpers ----------------
__device__ __forceinline__ float tanh_ap(float x) {
    float y; asm("tanh.approx.f32 %0, %1;" : "=f"(y) : "f"(x)); return y;
}
__device__ __forceinline__ float fsig(float x) {
    return fmaf(tanh_ap(0.5f * x), 0.5f, 0.5f);
}
// packed fp32x2 FMA (sm_100+): d = a*b + c
__device__ __forceinline__ float2 ffma2(float2 a, float2 b, float2 c) {
    float2 d;
    asm("{\n\t"
        ".reg .b64 Ra, Rb, Rc, Rd;\n\t"
        "mov.b64 Ra, {%2, %3};\n\t"
        "mov.b64 Rb, {%4, %5};\n\t"
        "mov.b64 Rc, {%6, %7};\n\t"
        "fma.rn.f32x2 Rd, Ra, Rb, Rc;\n\t"
        "mov.b64 {%0, %1}, Rd;\n\t"
        "}"
        : "=f"(d.x), "=f"(d.y)
        : "f"(a.x), "f"(a.y), "f"(b.x), "f"(b.y), "f"(c.x), "f"(c.y));
    return d;
}
__device__ __forceinline__ void cp16(void* smemDst, const void* gmemSrc) {
    unsigned sa = (unsigned)__cvta_generic_to_shared(smemDst);
    asm volatile("cp.async.cg.shared.global [%0], [%1], 16;\n" :: "r"(sa), "l"(gmemSrc));
}
#define CP_COMMIT() asm volatile("cp.async.commit_group;\n" ::)

// =====================================================================
// Kernel 1: xw1 = X @ W1. tf32 WMMA, 128x64 block tile, BK=32,
// 2-stage cp.async double buffer. 256 threads = 8 warps (4M x 2N),
// each warp 32x32 (2x2 wmma 16x16x8).
// =====================================================================
#define BM 128
#define BN 64
#define BK 32
#define ASTRIDE 40
#define BSTRIDE 72
#define GEMM_SMEM_FLOATS (2*BM*ASTRIDE + 2*BK*BSTRIDE)   // 10240 + 4608
#define GEMM_SMEM_BYTES  (GEMM_SMEM_FLOATS * 4)          // 59392

__global__ __launch_bounds__(256) void gemm1_kernel(
    const float* __restrict__ support,
    const float* __restrict__ query,
    const float* __restrict__ unlabel,
    const float* __restrict__ model,
    const float* __restrict__ W1)
{
    extern __shared__ float gsm[];
    float* As = gsm;                       // [2][BM*ASTRIDE]
    float* Bs = gsm + 2 * BM * ASTRIDE;    // [2][BK*BSTRIDE]

    const int bn = blockIdx.x;             // 0..7
    const int bm = blockIdx.y;             // 0..919
    const long row0 = (long)bm * BM;

    const float* A;
    long arow;
    if (row0 < ROW_SUP_END)      { A = support; arow = row0; }
    else if (row0 < ROW_QRY_END) { A = query;   arow = row0 - ROW_SUP_END; }
    else if (row0 < ROW_UNL_END) { A = unlabel; arow = row0 - ROW_QRY_END; }
    else                         { A = model;   arow = row0 - ROW_UNL_END; }
    const float* Abase = A + arow * E_DIM;

    const int tid  = threadIdx.x;
    const int warp = tid >> 5;
    const int wm   = warp & 3;    // 32-row slice
    const int wn   = warp >> 2;   // 32-col slice

    wmma::fragment<wmma::accumulator, 16, 16, 8, float> cf[2][2];
    #pragma unroll
    for (int i = 0; i < 2; i++)
        #pragma unroll
        for (int jj = 0; jj < 2; jj++)
            wmma::fill_fragment(cf[i][jj], 0.0f);

    auto load_stage = [&](int st, int k0) {
        float* Ad = As + st * (BM * ASTRIDE);
        float* Bd = Bs + st * (BK * BSTRIDE);
        #pragma unroll
        for (int i = 0; i < 4; i++) {              // 1024 f4 slots / 256 thr
            int idx = tid + i * 256;
            int r = idx >> 3, c = (idx & 7) * 4;
            cp16(&Ad[r * ASTRIDE + c], Abase + (long)r * E_DIM + k0 + c);
        }
        #pragma unroll
        for (int i = 0; i < 2; i++) {              // 512 f4 slots
            int idx = tid + i * 256;
            int r = idx >> 4, c = (idx & 15) * 4;
            cp16(&Bd[r * BSTRIDE + c], W1 + (long)(k0 + r) * G1 + bn * BN + c);
        }
        CP_COMMIT();
    };

    load_stage(0, 0);

    const int NKT = E_DIM / BK;   // 24
    for (int kt = 0; kt < NKT; kt++) {
        int st = kt & 1;
        if (kt < NKT - 1) {
            load_stage(st ^ 1, (kt + 1) * BK);
            asm volatile("cp.async.wait_group 1;\n" ::);
        } else {
            asm volatile("cp.async.wait_group 0;\n" ::);
        }
        __syncthreads();

        const float* Ac = As + st * (BM * ASTRIDE);
        const float* Bc = Bs + st * (BK * BSTRIDE);
        #pragma unroll
        for (int kk = 0; kk < 4; kk++) {
            wmma::fragment<wmma::matrix_a, 16, 16, 8, wmma::precision::tf32, wmma::row_major> af[2];
            #pragma unroll
            for (int i = 0; i < 2; i++) {
                wmma::load_matrix_sync(af[i], &Ac[(wm * 32 + i * 16) * ASTRIDE + kk * 8], ASTRIDE);
                #pragma unroll
                for (int e = 0; e < af[i].num_elements; e++)
                    af[i].x[e] = wmma::__float_to_tf32(af[i].x[e]);
            }
            wmma::fragment<wmma::matrix_b, 16, 16, 8, wmma::precision::tf32, wmma::row_major> bf[2];
            #pragma unroll
            for (int jj = 0; jj < 2; jj++) {
                wmma::load_matrix_sync(bf[jj], &Bc[(kk * 8) * BSTRIDE + wn * 32 + jj * 16], BSTRIDE);
                #pragma unroll
                for (int e = 0; e < bf[jj].num_elements; e++)
                    bf[jj].x[e] = wmma::__float_to_tf32(bf[jj].x[e]);
            }
            #pragma unroll
            for (int i = 0; i < 2; i++)
                #pragma unroll
                for (int jj = 0; jj < 2; jj++)
                    wmma::mma_sync(cf[i][jj], af[i], bf[jj], cf[i][jj]);
        }
        __syncthreads();
    }

    #pragma unroll
    for (int i = 0; i < 2; i++)
        #pragma unroll
        for (int jj = 0; jj < 2; jj++) {
            float* dst = &g_xw1[(row0 + wm * 32 + i * 16) * (long)G1 + bn * BN + wn * 32 + jj * 16];
            wmma::store_matrix_sync(dst, cf[i][jj], G1, wmma::mem_row_major);
        }
}

// =====================================================================
// Kernel 2: fused LSTM1+LSTM2. 115 blocks x 512 threads, 8 seqs/block.
// FFMA2 (fp32x2) matvecs; U1 register-batched (MLP=16) from L2.
// smem layout identical to R1 (222208 B).
// =====================================================================
#define LSTM_SMEM_FLOATS 55552
#define LSTM_SMEM_BYTES  (LSTM_SMEM_FLOATS * 4)

__global__ __launch_bounds__(LSTM_THREADS) void lstm_kernel(
    const float* __restrict__ U1,
    const float* __restrict__ b1,
    const float* __restrict__ W2,
    const float* __restrict__ U2,
    const float* __restrict__ b2)
{
    extern __shared__ float sm[];
    float* sW2  = sm;
    float* sU2  = sm + 32768;
    float* zbuf = sm + 49152;
    float* h1T  = sm + 53248;
    float* h2T  = sm + 54272;
    float* sb1  = sm + 54784;
    float* sb2  = sm + 55296;

    const int tid = threadIdx.x;
    const long qbase = (long)blockIdx.x * SEQ_PER_BLOCK;

    {
        const float4* s4 = (const float4*)W2;
        float4* d4 = (float4*)sW2;
        for (int i = tid; i < (H1 * G2) / 4; i += LSTM_THREADS) d4[i] = s4[i];
        s4 = (const float4*)U2; d4 = (float4*)sU2;
        for (int i = tid; i < (H2 * G2) / 4; i += LSTM_THREADS) d4[i] = s4[i];
        sb1[tid] = b1[tid];
        if (tid < G2) sb2[tid] = b2[tid];
        for (int i = tid; i < 128 * 8; i += LSTM_THREADS) h1T[i] = 0.0f;
        if (tid < 64 * 8) h2T[tid] = 0.0f;
    }
    __syncthreads();

    float c1a = 0.0f, c1b = 0.0f, c2 = 0.0f;

    const int j  = tid;
    const int j2 = tid & 255;
    const int s0 = (tid >> 8) * 4;

    const int p0s = tid >> 7, p0n = tid & 127;
    const int p1s = 4 + (tid >> 7), p1n = tid & 127;
    const int u2s = tid >> 6, u2n = tid & 63;

    const float* xp0 = g_xw1 + (qbase * T_LEN) * (long)G1 + j;
    const float* U1j = U1 + j;

    for (int t = 0; t < T_LEN; t++) {
        // ---------- Phase A: z1 = xw1_t + b1 + h1 @ U1 ----------
        const float bb = sb1[j];
        const float* xp = xp0 + (long)t * G1;
        float2 a01 = make_float2(xp[0]           + bb, xp[1L * T_LEN * G1] + bb);
        float2 a23 = make_float2(xp[2L*T_LEN*G1] + bb, xp[3L * T_LEN * G1] + bb);
        float2 a45 = make_float2(xp[4L*T_LEN*G1] + bb, xp[5L * T_LEN * G1] + bb);
        float2 a67 = make_float2(xp[6L*T_LEN*G1] + bb, xp[7L * T_LEN * G1] + bb);

        #pragma unroll 1
        for (int kb = 0; kb < H1; kb += 16) {
            float u[16];
            #pragma unroll
            for (int i = 0; i < 16; i++) u[i] = U1j[(kb + i) * G1];
            #pragma unroll
            for (int i = 0; i < 16; i++) {
                float4 ha = *(const float4*)&h1T[(kb + i) * 8];
                float4 hb = *(const float4*)&h1T[(kb + i) * 8 + 4];
                float2 uu = make_float2(u[i], u[i]);
                a01 = ffma2(make_float2(ha.x, ha.y), uu, a01);
                a23 = ffma2(make_float2(ha.z, ha.w), uu, a23);
                a45 = ffma2(make_float2(hb.x, hb.y), uu, a45);
                a67 = ffma2(make_float2(hb.z, hb.w), uu, a67);
            }
        }
        zbuf[0 * G1 + j] = a01.x; zbuf[1 * G1 + j] = a01.y;
        zbuf[2 * G1 + j] = a23.x; zbuf[3 * G1 + j] = a23.y;
        zbuf[4 * G1 + j] = a45.x; zbuf[5 * G1 + j] = a45.y;
        zbuf[6 * G1 + j] = a67.x; zbuf[7 * G1 + j] = a67.y;
        __syncthreads();

        // ---------- LSTM1 update (2 states per thread) ----------
        {
            const float* zb = &zbuf[p0s * G1];
            float zi = zb[p0n], zf = zb[128 + p0n], zg = zb[256 + p0n], zo = zb[384 + p0n];
            c1a = fsig(zf) * c1a + fsig(zi) * tanh_ap(zg);
            h1T[p0n * 8 + p0s] = fsig(zo) * tanh_ap(c1a);
        }
        {
            const float* zb = &zbuf[p1s * G1];
            float zi = zb[p1n], zf = zb[128 + p1n], zg = zb[256 + p1n], zo = zb[384 + p1n];
            c1b = fsig(zf) * c1b + fsig(zi) * tanh_ap(zg);
            h1T[p1n * 8 + p1s] = fsig(zo) * tanh_ap(c1b);
        }
        __syncthreads();

        // ---------- Phase B: z2 = b2 + h1 @ W2 + h2 @ U2 ----------
        float2 acc2a = make_float2(sb2[j2], sb2[j2]);
        float2 acc2b = acc2a;

        #pragma unroll 8
        for (int k = 0; k < H1; k++) {
            float4 h4 = *(const float4*)&h1T[k * 8 + s0];
            float wv = sW2[k * G2 + j2];
            float2 ww = make_float2(wv, wv);
            acc2a = ffma2(make_float2(h4.x, h4.y), ww, acc2a);
            acc2b = ffma2(make_float2(h4.z, h4.w), ww, acc2b);
        }
        #pragma unroll 8
        for (int k = 0; k < H2; k++) {
            float4 h4 = *(const float4*)&h2T[k * 8 + s0];
            float uv = sU2[k * G2 + j2];
            float2 uu = make_float2(uv, uv);
            acc2a = ffma2(make_float2(h4.x, h4.y), uu, acc2a);
            acc2b = ffma2(make_float2(h4.z, h4.w), uu, acc2b);
        }
        zbuf[(s0 + 0) * G2 + j2] = acc2a.x;
        zbuf[(s0 + 1) * G2 + j2] = acc2a.y;
        zbuf[(s0 + 2) * G2 + j2] = acc2b.x;
        zbuf[(s0 + 3) * G2 + j2] = acc2b.y;
        __syncthreads();

        // ---------- LSTM2 update ----------
        {
            const float* zb = &zbuf[u2s * G2];
            float zi = zb[u2n], zf = zb[64 + u2n], zg = zb[128 + u2n], zo = zb[192 + u2n];
            c2 = fsig(zf) * c2 + fsig(zi) * tanh_ap(zg);
            h2T[u2n * 8 + u2s] = fsig(zo) * tanh_ap(c2);
        }
        __syncthreads();
    }

    g_enc[(qbase + u2s) * H2 + u2n] = h2T[u2n * 8 + u2s];
}

// =====================================================================
// Kernel 3: heads
// =====================================================================
__global__ __launch_bounds__(128) void head_kernel(
    int encBase, int groupPerBatch,
    const float* __restrict__ W, const float* __restrict__ b,
    const float* __restrict__ g, const float* __restrict__ beta,
    const float* __restrict__ m, const float* __restrict__ v,
    float* __restrict__ out)
{
    __shared__ float x[128];
    const int row = blockIdx.x;
    const int tid = threadIdx.x;
    const int bidx = row / groupPerBatch;

    if (tid < 64) x[tid] = g_enc[(encBase + row) * H2 + tid];
    else          x[tid] = g_enc[(912 + bidx) * H2 + (tid - 64)];
    __syncthreads();

    if (tid < 32) {
        float acc = b[tid];
        #pragma unroll 8
        for (int k = 0; k < 128; k++) acc = fmaf(x[k], W[k * 32 + tid], acc);
        float y = fmaxf(acc, 0.0f);
        out[row * 32 + tid] = g[tid] * (y - m[tid]) * rsqrtf(v[tid] + 1e-3f) + beta[tid];
    }
}

// =====================================================================
extern "C" void kernel_launch(void* const* d_in, const int* in_sizes, int n_in,
                              void* d_out, int out_size)
{
    (void)in_sizes; (void)n_in; (void)out_size;

    const float* support = (const float*)d_in[0];
    const float* query   = (const float*)d_in[1];
    const float* unlabel = (const float*)d_in[2];
    const float* model   = (const float*)d_in[3];
    const float* W1 = (const float*)d_in[4];
    const float* U1 = (const float*)d_in[5];
    const float* b1 = (const float*)d_in[6];
    const float* W2 = (const float*)d_in[7];
    const float* U2 = (const float*)d_in[8];
    const float* b2 = (const float*)d_in[9];
    float* out = (float*)d_out;

    cudaFuncSetAttribute(gemm1_kernel,
                         cudaFuncAttributeMaxDynamicSharedMemorySize,
                         GEMM_SMEM_BYTES);
    dim3 ggrid(G1 / BN, MROWS / BM);   // (8, 920)
    gemm1_kernel<<<ggrid, 256, GEMM_SMEM_BYTES>>>(support, query, unlabel, model, W1);

    cudaFuncSetAttribute(lstm_kernel,
                         cudaFuncAttributeMaxDynamicSharedMemorySize,
                         LSTM_SMEM_BYTES);
    lstm_kernel<<<NSEQ / SEQ_PER_BLOCK, LSTM_THREADS, LSTM_SMEM_BYTES>>>(
        U1, b1, W2, U2, b2);

    head_kernel<<<200, 128>>>(0, 25,
        (const float*)d_in[10], (const float*)d_in[11], (const float*)d_in[12],
        (const float*)d_in[13], (const float*)d_in[14], (const float*)d_in[15],
        out);
    head_kernel<<<200, 128>>>(200, 25,
        (const float*)d_in[16], (const float*)d_in[17], (const float*)d_in[18],
        (const float*)d_in[19], (const float*)d_in[20], (const float*)d_in[21],
        out + 200 * 32);
    head_kernel<<<512, 128>>>(400, 64,
        (const float*)d_in[22], (const float*)d_in[23], (const float*)d_in[24],
        (const float*)d_in[25], (const float*)d_in[26], (const float*)d_in[27],
        out + 400 * 32);
}

// round 6
// speedup vs baseline: 1.5526x; 1.0376x over previous
#include <cuda_runtime.h>
#include <cuda_bf16.h>
#include <mma.h>
#include <cstdint>

using namespace nvcuda;

// ---------------- problem constants ----------------
#define T_LEN   128
#define E_DIM   768
#define H1      128
#define H2      64
#define G1      512   // 4*H1
#define G2      256   // 4*H2
#define NSEQ    920
#define MROWS   (NSEQ * T_LEN)   // 117760
#define SEQ_PER_BLOCK 8
#define LSTM_THREADS  512

#define ROW_SUP_END 25600
#define ROW_QRY_END 51200
#define ROW_UNL_END 116736

// ---------------- scratch ----------------
__device__ float g_xw1[(long)MROWS * G1];   // 241 MB
__device__ float g_enc[NSEQ * H2];

// ---------------- helpers ----------------
__device__ __forceinline__ float tanh_ap(float x) {
    float y; asm("tanh.approx.f32 %0, %1;" : "=f"(y) : "f"(x)); return y;
}
__device__ __forceinline__ float fsig(float x) {
    return fmaf(tanh_ap(0.5f * x), 0.5f, 0.5f);
}
__device__ __forceinline__ float2 ffma2(float2 a, float2 b, float2 c) {
    float2 d;
    asm("{\n\t"
        ".reg .b64 Ra, Rb, Rc, Rd;\n\t"
        "mov.b64 Ra, {%2, %3};\n\t"
        "mov.b64 Rb, {%4, %5};\n\t"
        "mov.b64 Rc, {%6, %7};\n\t"
        "fma.rn.f32x2 Rd, Ra, Rb, Rc;\n\t"
        "mov.b64 {%0, %1}, Rd;\n\t"
        "}"
        : "=f"(d.x), "=f"(d.y)
        : "f"(a.x), "f"(a.y), "f"(b.x), "f"(b.y), "f"(c.x), "f"(c.y));
    return d;
}
__device__ __forceinline__ void cp16(void* smemDst, const void* gmemSrc) {
    unsigned sa = (unsigned)__cvta_generic_to_shared(smemDst);
    asm volatile("cp.async.cg.shared.global [%0], [%1], 16;\n" :: "r"(sa), "l"(gmemSrc));
}
#define CP_COMMIT() asm volatile("cp.async.commit_group;\n" ::)

// =====================================================================
// Kernel 1: xw1 = X @ W1. tf32 WMMA, CTA tile 128x128, BK=32,
// 2-stage cp.async. 256 threads = 8 warps (4M x 2N), warp tile 32x64
// (2x4 wmma 16x16x8 accumulators). 2 CTAs/SM.
// =====================================================================
#define BM 128
#define BN 128
#define BK 32
#define ASTRIDE 40
#define BSTRIDE 136
#define GEMM_SMEM_FLOATS (2*BM*ASTRIDE + 2*BK*BSTRIDE)   // 10240 + 8704
#define GEMM_SMEM_BYTES  (GEMM_SMEM_FLOATS * 4)          // 75776

__global__ __launch_bounds__(256, 2) void gemm1_kernel(
    const float* __restrict__ support,
    const float* __restrict__ query,
    const float* __restrict__ unlabel,
    const float* __restrict__ model,
    const float* __restrict__ W1)
{
    extern __shared__ float gsm[];
    float* As = gsm;                       // [2][BM*ASTRIDE]
    float* Bs = gsm + 2 * BM * ASTRIDE;    // [2][BK*BSTRIDE]

    const int bn = blockIdx.x;             // 0..3
    const int bm = blockIdx.y;             // 0..919
    const long row0 = (long)bm * BM;

    const float* A;
    long arow;
    if (row0 < ROW_SUP_END)      { A = support; arow = row0; }
    else if (row0 < ROW_QRY_END) { A = query;   arow = row0 - ROW_SUP_END; }
    else if (row0 < ROW_UNL_END) { A = unlabel; arow = row0 - ROW_QRY_END; }
    else                         { A = model;   arow = row0 - ROW_UNL_END; }
    const float* Abase = A + arow * E_DIM;

    const int tid  = threadIdx.x;
    const int warp = tid >> 5;
    const int wm   = warp & 3;    // 32-row slice
    const int wn   = warp >> 2;   // 64-col slice

    wmma::fragment<wmma::accumulator, 16, 16, 8, float> cf[2][4];
    #pragma unroll
    for (int i = 0; i < 2; i++)
        #pragma unroll
        for (int jj = 0; jj < 4; jj++)
            wmma::fill_fragment(cf[i][jj], 0.0f);

    auto load_stage = [&](int st, int k0) {
        float* Ad = As + st * (BM * ASTRIDE);
        float* Bd = Bs + st * (BK * BSTRIDE);
        #pragma unroll
        for (int i = 0; i < 4; i++) {              // A: 1024 f4 slots
            int idx = tid + i * 256;
            int r = idx >> 3, c = (idx & 7) * 4;
            cp16(&Ad[r * ASTRIDE + c], Abase + (long)r * E_DIM + k0 + c);
        }
        #pragma unroll
        for (int i = 0; i < 4; i++) {              // B: 1024 f4 slots
            int idx = tid + i * 256;
            int r = idx >> 5, c = (idx & 31) * 4;
            cp16(&Bd[r * BSTRIDE + c], W1 + (long)(k0 + r) * G1 + bn * BN + c);
        }
        CP_COMMIT();
    };

    load_stage(0, 0);

    const int NKT = E_DIM / BK;   // 24
    for (int kt = 0; kt < NKT; kt++) {
        int st = kt & 1;
        if (kt < NKT - 1) {
            load_stage(st ^ 1, (kt + 1) * BK);
            asm volatile("cp.async.wait_group 1;\n" ::);
        } else {
            asm volatile("cp.async.wait_group 0;\n" ::);
        }
        __syncthreads();

        const float* Ac = As + st * (BM * ASTRIDE);
        const float* Bc = Bs + st * (BK * BSTRIDE);
        #pragma unroll
        for (int kk = 0; kk < 4; kk++) {
            wmma::fragment<wmma::matrix_a, 16, 16, 8, wmma::precision::tf32, wmma::row_major> af[2];
            #pragma unroll
            for (int i = 0; i < 2; i++) {
                wmma::load_matrix_sync(af[i], &Ac[(wm * 32 + i * 16) * ASTRIDE + kk * 8], ASTRIDE);
                #pragma unroll
                for (int e = 0; e < af[i].num_elements; e++)
                    af[i].x[e] = wmma::__float_to_tf32(af[i].x[e]);
            }
            #pragma unroll
            for (int jj = 0; jj < 4; jj++) {
                wmma::fragment<wmma::matrix_b, 16, 16, 8, wmma::precision::tf32, wmma::row_major> bf;
                wmma::load_matrix_sync(bf, &Bc[(kk * 8) * BSTRIDE + wn * 64 + jj * 16], BSTRIDE);
                #pragma unroll
                for (int e = 0; e < bf.num_elements; e++)
                    bf.x[e] = wmma::__float_to_tf32(bf.x[e]);
                #pragma unroll
                for (int i = 0; i < 2; i++)
                    wmma::mma_sync(cf[i][jj], af[i], bf, cf[i][jj]);
            }
        }
        __syncthreads();
    }

    #pragma unroll
    for (int i = 0; i < 2; i++)
        #pragma unroll
        for (int jj = 0; jj < 4; jj++) {
            float* dst = &g_xw1[(row0 + wm * 32 + i * 16) * (long)G1 + bn * BN + wn * 64 + jj * 16];
            wmma::store_matrix_sync(dst, cf[i][jj], G1, wmma::mem_row_major);
        }
}

// =====================================================================
// Kernel 2: fused LSTM1+LSTM2 (unchanged from R3 — passed at 2828)
// =====================================================================
#define LSTM_SMEM_FLOATS 55552
#define LSTM_SMEM_BYTES  (LSTM_SMEM_FLOATS * 4)

__global__ __launch_bounds__(LSTM_THREADS) void lstm_kernel(
    const float* __restrict__ U1,
    const float* __restrict__ b1,
    const float* __restrict__ W2,
    const float* __restrict__ U2,
    const float* __restrict__ b2)
{
    extern __shared__ float sm[];
    float* sW2  = sm;
    float* sU2  = sm + 32768;
    float* zbuf = sm + 49152;
    float* h1T  = sm + 53248;
    float* h2T  = sm + 54272;
    float* sb1  = sm + 54784;
    float* sb2  = sm + 55296;

    const int tid = threadIdx.x;
    const long qbase = (long)blockIdx.x * SEQ_PER_BLOCK;

    {
        const float4* s4 = (const float4*)W2;
        float4* d4 = (float4*)sW2;
        for (int i = tid; i < (H1 * G2) / 4; i += LSTM_THREADS) d4[i] = s4[i];
        s4 = (const float4*)U2; d4 = (float4*)sU2;
        for (int i = tid; i < (H2 * G2) / 4; i += LSTM_THREADS) d4[i] = s4[i];
        sb1[tid] = b1[tid];
        if (tid < G2) sb2[tid] = b2[tid];
        for (int i = tid; i < 128 * 8; i += LSTM_THREADS) h1T[i] = 0.0f;
        if (tid < 64 * 8) h2T[tid] = 0.0f;
    }
    __syncthreads();

    float c1a = 0.0f, c1b = 0.0f, c2 = 0.0f;

    const int j  = tid;
    const int j2 = tid & 255;
    const int s0 = (tid >> 8) * 4;

    const int p0s = tid >> 7, p0n = tid & 127;
    const int p1s = 4 + (tid >> 7), p1n = tid & 127;
    const int u2s = tid >> 6, u2n = tid & 63;

    const float* xp0 = g_xw1 + (qbase * T_LEN) * (long)G1 + j;
    const float* U1j = U1 + j;

    for (int t = 0; t < T_LEN; t++) {
        // ---------- Phase A: z1 = xw1_t + b1 + h1 @ U1 ----------
        const float bb = sb1[j];
        const float* xp = xp0 + (long)t * G1;
        float2 a01 = make_float2(xp[0]           + bb, xp[1L * T_LEN * G1] + bb);
        float2 a23 = make_float2(xp[2L*T_LEN*G1] + bb, xp[3L * T_LEN * G1] + bb);
        float2 a45 = make_float2(xp[4L*T_LEN*G1] + bb, xp[5L * T_LEN * G1] + bb);
        float2 a67 = make_float2(xp[6L*T_LEN*G1] + bb, xp[7L * T_LEN * G1] + bb);

        #pragma unroll 1
        for (int kb = 0; kb < H1; kb += 16) {
            float u[16];
            #pragma unroll
            for (int i = 0; i < 16; i++) u[i] = U1j[(kb + i) * G1];
            #pragma unroll
            for (int i = 0; i < 16; i++) {
                float4 ha = *(const float4*)&h1T[(kb + i) * 8];
                float4 hb = *(const float4*)&h1T[(kb + i) * 8 + 4];
                float2 uu = make_float2(u[i], u[i]);
                a01 = ffma2(make_float2(ha.x, ha.y), uu, a01);
                a23 = ffma2(make_float2(ha.z, ha.w), uu, a23);
                a45 = ffma2(make_float2(hb.x, hb.y), uu, a45);
                a67 = ffma2(make_float2(hb.z, hb.w), uu, a67);
            }
        }
        zbuf[0 * G1 + j] = a01.x; zbuf[1 * G1 + j] = a01.y;
        zbuf[2 * G1 + j] = a23.x; zbuf[3 * G1 + j] = a23.y;
        zbuf[4 * G1 + j] = a45.x; zbuf[5 * G1 + j] = a45.y;
        zbuf[6 * G1 + j] = a67.x; zbuf[7 * G1 + j] = a67.y;
        __syncthreads();

        // ---------- LSTM1 update ----------
        {
            const float* zb = &zbuf[p0s * G1];
            float zi = zb[p0n], zf = zb[128 + p0n], zg = zb[256 + p0n], zo = zb[384 + p0n];
            c1a = fsig(zf) * c1a + fsig(zi) * tanh_ap(zg);
            h1T[p0n * 8 + p0s] = fsig(zo) * tanh_ap(c1a);
        }
        {
            const float* zb = &zbuf[p1s * G1];
            float zi = zb[p1n], zf = zb[128 + p1n], zg = zb[256 + p1n], zo = zb[384 + p1n];
            c1b = fsig(zf) * c1b + fsig(zi) * tanh_ap(zg);
            h1T[p1n * 8 + p1s] = fsig(zo) * tanh_ap(c1b);
        }
        __syncthreads();

        // ---------- Phase B: z2 = b2 + h1 @ W2 + h2 @ U2 ----------
        float2 acc2a = make_float2(sb2[j2], sb2[j2]);
        float2 acc2b = acc2a;

        #pragma unroll 8
        for (int k = 0; k < H1; k++) {
            float4 h4 = *(const float4*)&h1T[k * 8 + s0];
            float wv = sW2[k * G2 + j2];
            float2 ww = make_float2(wv, wv);
            acc2a = ffma2(make_float2(h4.x, h4.y), ww, acc2a);
            acc2b = ffma2(make_float2(h4.z, h4.w), ww, acc2b);
        }
        #pragma unroll 8
        for (int k = 0; k < H2; k++) {
            float4 h4 = *(const float4*)&h2T[k * 8 + s0];
            float uv = sU2[k * G2 + j2];
            float2 uu = make_float2(uv, uv);
            acc2a = ffma2(make_float2(h4.x, h4.y), uu, acc2a);
            acc2b = ffma2(make_float2(h4.z, h4.w), uu, acc2b);
        }
        zbuf[(s0 + 0) * G2 + j2] = acc2a.x;
        zbuf[(s0 + 1) * G2 + j2] = acc2a.y;
        zbuf[(s0 + 2) * G2 + j2] = acc2b.x;
        zbuf[(s0 + 3) * G2 + j2] = acc2b.y;
        __syncthreads();

        // ---------- LSTM2 update ----------
        {
            const float* zb = &zbuf[u2s * G2];
            float zi = zb[u2n], zf = zb[64 + u2n], zg = zb[128 + u2n], zo = zb[192 + u2n];
            c2 = fsig(zf) * c2 + fsig(zi) * tanh_ap(zg);
            h2T[u2n * 8 + u2s] = fsig(zo) * tanh_ap(c2);
        }
        __syncthreads();
    }

    g_enc[(qbase + u2s) * H2 + u2n] = h2T[u2n * 8 + u2s];
}

// =====================================================================
// Kernel 3: heads (unchanged)
// =====================================================================
__global__ __launch_bounds__(128) void head_kernel(
    int encBase, int groupPerBatch,
    const float* __restrict__ W, const float* __restrict__ b,
    const float* __restrict__ g, const float* __restrict__ beta,
    const float* __restrict__ m, const float* __restrict__ v,
    float* __restrict__ out)
{
    __shared__ float x[128];
    const int row = blockIdx.x;
    const int tid = threadIdx.x;
    const int bidx = row / groupPerBatch;

    if (tid < 64) x[tid] = g_enc[(encBase + row) * H2 + tid];
    else          x[tid] = g_enc[(912 + bidx) * H2 + (tid - 64)];
    __syncthreads();

    if (tid < 32) {
        float acc = b[tid];
        #pragma unroll 8
        for (int k = 0; k < 128; k++) acc = fmaf(x[k], W[k * 32 + tid], acc);
        float y = fmaxf(acc, 0.0f);
        out[row * 32 + tid] = g[tid] * (y - m[tid]) * rsqrtf(v[tid] + 1e-3f) + beta[tid];
    }
}

// =====================================================================
extern "C" void kernel_launch(void* const* d_in, const int* in_sizes, int n_in,
                              void* d_out, int out_size)
{
    (void)in_sizes; (void)n_in; (void)out_size;

    const float* support = (const float*)d_in[0];
    const float* query   = (const float*)d_in[1];
    const float* unlabel = (const float*)d_in[2];
    const float* model   = (const float*)d_in[3];
    const float* W1 = (const float*)d_in[4];
    const float* U1 = (const float*)d_in[5];
    const float* b1 = (const float*)d_in[6];
    const float* W2 = (const float*)d_in[7];
    const float* U2 = (const float*)d_in[8];
    const float* b2 = (const float*)d_in[9];
    float* out = (float*)d_out;

    cudaFuncSetAttribute(gemm1_kernel,
                         cudaFuncAttributeMaxDynamicSharedMemorySize,
                         GEMM_SMEM_BYTES);
    dim3 ggrid(G1 / BN, MROWS / BM);   // (4, 920)
    gemm1_kernel<<<ggrid, 256, GEMM_SMEM_BYTES>>>(support, query, unlabel, model, W1);

    cudaFuncSetAttribute(lstm_kernel,
                         cudaFuncAttributeMaxDynamicSharedMemorySize,
                         LSTM_SMEM_BYTES);
    lstm_kernel<<<NSEQ / SEQ_PER_BLOCK, LSTM_THREADS, LSTM_SMEM_BYTES>>>(
        U1, b1, W2, U2, b2);

    head_kernel<<<200, 128>>>(0, 25,
        (const float*)d_in[10], (const float*)d_in[11], (const float*)d_in[12],
        (const float*)d_in[13], (const float*)d_in[14], (const float*)d_in[15],
        out);
    head_kernel<<<200, 128>>>(200, 25,
        (const float*)d_in[16], (const float*)d_in[17], (const float*)d_in[18],
        (const float*)d_in[19], (const float*)d_in[20], (const float*)d_in[21],
        out + 200 * 32);
    head_kernel<<<512, 128>>>(400, 64,
        (const float*)d_in[22], (const float*)d_in[23], (const float*)d_in[24],
        (const float*)d_in[25], (const float*)d_in[26], (const float*)d_in[27],
        out + 400 * 32);
}

// round 7
// speedup vs baseline: 1.6042x; 1.0332x over previous
#include <cuda_runtime.h>
#include <cuda_bf16.h>
#include <mma.h>
#include <cstdint>

using namespace nvcuda;

// ---------------- problem constants ----------------
#define T_LEN   128
#define E_DIM   768
#define H1      128
#define H2      64
#define G1      512   // 4*H1
#define G2      256   // 4*H2
#define NSEQ    920
#define MROWS   (NSEQ * T_LEN)   // 117760
#define SEQ_PER_BLOCK 8
#define LSTM_THREADS  512

#define ROW_SUP_END 25600
#define ROW_QRY_END 51200
#define ROW_UNL_END 116736

// ---------------- scratch ----------------
__device__ float g_xw1[(long)MROWS * G1];   // 241 MB
__device__ float g_enc[NSEQ * H2];

// ---------------- helpers ----------------
typedef unsigned long long u64t;

__device__ __forceinline__ float tanh_ap(float x) {
    float y; asm("tanh.approx.f32 %0, %1;" : "=f"(y) : "f"(x)); return y;
}
__device__ __forceinline__ float fsig(float x) {
    return fmaf(tanh_ap(0.5f * x), 0.5f, 0.5f);
}
// packed f32x2 ops: operands STAY in b64 registers (no per-op pack/unpack)
__device__ __forceinline__ u64t ffma2p(u64t a, u64t b, u64t c) {
    u64t d;
    asm("fma.rn.f32x2 %0, %1, %2, %3;" : "=l"(d) : "l"(a), "l"(b), "l"(c));
    return d;
}
__device__ __forceinline__ u64t pack2(float x, float y) {
    u64t d; asm("mov.b64 %0, {%1, %2};" : "=l"(d) : "f"(x), "f"(y)); return d;
}
__device__ __forceinline__ void unpack2(u64t v, float& x, float& y) {
    asm("mov.b64 {%0, %1}, %2;" : "=f"(x), "=f"(y) : "l"(v));
}
__device__ __forceinline__ void cp16(void* smemDst, const void* gmemSrc) {
    unsigned sa = (unsigned)__cvta_generic_to_shared(smemDst);
    asm volatile("cp.async.cg.shared.global [%0], [%1], 16;\n" :: "r"(sa), "l"(gmemSrc));
}
#define CP_COMMIT() asm volatile("cp.async.commit_group;\n" ::)

// =====================================================================
// Kernel 1: xw1 = X @ W1. tf32 WMMA, CTA tile 128x128, BK=32,
// 2-stage cp.async. 256 threads = 8 warps (4M x 2N), warp tile 32x64.
// (unchanged from R5)
// =====================================================================
#define BM 128
#define BN 128
#define BK 32
#define ASTRIDE 40
#define BSTRIDE 136
#define GEMM_SMEM_FLOATS (2*BM*ASTRIDE + 2*BK*BSTRIDE)
#define GEMM_SMEM_BYTES  (GEMM_SMEM_FLOATS * 4)          // 75776

__global__ __launch_bounds__(256, 2) void gemm1_kernel(
    const float* __restrict__ support,
    const float* __restrict__ query,
    const float* __restrict__ unlabel,
    const float* __restrict__ model,
    const float* __restrict__ W1)
{
    extern __shared__ float gsm[];
    float* As = gsm;
    float* Bs = gsm + 2 * BM * ASTRIDE;

    const int bn = blockIdx.x;
    const int bm = blockIdx.y;
    const long row0 = (long)bm * BM;

    const float* A;
    long arow;
    if (row0 < ROW_SUP_END)      { A = support; arow = row0; }
    else if (row0 < ROW_QRY_END) { A = query;   arow = row0 - ROW_SUP_END; }
    else if (row0 < ROW_UNL_END) { A = unlabel; arow = row0 - ROW_QRY_END; }
    else                         { A = model;   arow = row0 - ROW_UNL_END; }
    const float* Abase = A + arow * E_DIM;

    const int tid  = threadIdx.x;
    const int warp = tid >> 5;
    const int wm   = warp & 3;
    const int wn   = warp >> 2;

    wmma::fragment<wmma::accumulator, 16, 16, 8, float> cf[2][4];
    #pragma unroll
    for (int i = 0; i < 2; i++)
        #pragma unroll
        for (int jj = 0; jj < 4; jj++)
            wmma::fill_fragment(cf[i][jj], 0.0f);

    auto load_stage = [&](int st, int k0) {
        float* Ad = As + st * (BM * ASTRIDE);
        float* Bd = Bs + st * (BK * BSTRIDE);
        #pragma unroll
        for (int i = 0; i < 4; i++) {
            int idx = tid + i * 256;
            int r = idx >> 3, c = (idx & 7) * 4;
            cp16(&Ad[r * ASTRIDE + c], Abase + (long)r * E_DIM + k0 + c);
        }
        #pragma unroll
        for (int i = 0; i < 4; i++) {
            int idx = tid + i * 256;
            int r = idx >> 5, c = (idx & 31) * 4;
            cp16(&Bd[r * BSTRIDE + c], W1 + (long)(k0 + r) * G1 + bn * BN + c);
        }
        CP_COMMIT();
    };

    load_stage(0, 0);

    const int NKT = E_DIM / BK;
    for (int kt = 0; kt < NKT; kt++) {
        int st = kt & 1;
        if (kt < NKT - 1) {
            load_stage(st ^ 1, (kt + 1) * BK);
            asm volatile("cp.async.wait_group 1;\n" ::);
        } else {
            asm volatile("cp.async.wait_group 0;\n" ::);
        }
        __syncthreads();

        const float* Ac = As + st * (BM * ASTRIDE);
        const float* Bc = Bs + st * (BK * BSTRIDE);
        #pragma unroll
        for (int kk = 0; kk < 4; kk++) {
            wmma::fragment<wmma::matrix_a, 16, 16, 8, wmma::precision::tf32, wmma::row_major> af[2];
            #pragma unroll
            for (int i = 0; i < 2; i++) {
                wmma::load_matrix_sync(af[i], &Ac[(wm * 32 + i * 16) * ASTRIDE + kk * 8], ASTRIDE);
                #pragma unroll
                for (int e = 0; e < af[i].num_elements; e++)
                    af[i].x[e] = wmma::__float_to_tf32(af[i].x[e]);
            }
            #pragma unroll
            for (int jj = 0; jj < 4; jj++) {
                wmma::fragment<wmma::matrix_b, 16, 16, 8, wmma::precision::tf32, wmma::row_major> bf;
                wmma::load_matrix_sync(bf, &Bc[(kk * 8) * BSTRIDE + wn * 64 + jj * 16], BSTRIDE);
                #pragma unroll
                for (int e = 0; e < bf.num_elements; e++)
                    bf.x[e] = wmma::__float_to_tf32(bf.x[e]);
                #pragma unroll
                for (int i = 0; i < 2; i++)
                    wmma::mma_sync(cf[i][jj], af[i], bf, cf[i][jj]);
            }
        }
        __syncthreads();
    }

    #pragma unroll
    for (int i = 0; i < 2; i++)
        #pragma unroll
        for (int jj = 0; jj < 4; jj++) {
            float* dst = &g_xw1[(row0 + wm * 32 + i * 16) * (long)G1 + bn * BN + wn * 64 + jj * 16];
            wmma::store_matrix_sync(dst, cf[i][jj], G1, wmma::mem_row_major);
        }
}

// =====================================================================
// Kernel 2: fused LSTM1+LSTM2, packed-f32x2 matvecs (accumulators stay
// in b64 registers across the whole k-loop; h tiles loaded as ulonglong2).
// =====================================================================
#define LSTM_SMEM_FLOATS 55552
#define LSTM_SMEM_BYTES  (LSTM_SMEM_FLOATS * 4)

__global__ __launch_bounds__(LSTM_THREADS) void lstm_kernel(
    const float* __restrict__ U1,
    const float* __restrict__ b1,
    const float* __restrict__ W2,
    const float* __restrict__ U2,
    const float* __restrict__ b2)
{
    extern __shared__ float sm[];
    float* sW2  = sm;
    float* sU2  = sm + 32768;
    float* zbuf = sm + 49152;
    float* h1T  = sm + 53248;
    float* h2T  = sm + 54272;
    float* sb1  = sm + 54784;
    float* sb2  = sm + 55296;

    const int tid = threadIdx.x;
    const long qbase = (long)blockIdx.x * SEQ_PER_BLOCK;

    {
        const float4* s4 = (const float4*)W2;
        float4* d4 = (float4*)sW2;
        for (int i = tid; i < (H1 * G2) / 4; i += LSTM_THREADS) d4[i] = s4[i];
        s4 = (const float4*)U2; d4 = (float4*)sU2;
        for (int i = tid; i < (H2 * G2) / 4; i += LSTM_THREADS) d4[i] = s4[i];
        sb1[tid] = b1[tid];
        if (tid < G2) sb2[tid] = b2[tid];
        for (int i = tid; i < 128 * 8; i += LSTM_THREADS) h1T[i] = 0.0f;
        if (tid < 64 * 8) h2T[tid] = 0.0f;
    }
    __syncthreads();

    float c1a = 0.0f, c1b = 0.0f, c2 = 0.0f;

    const int j  = tid;
    const int j2 = tid & 255;
    const int s0 = (tid >> 8) * 4;

    const int p0s = tid >> 7, p0n = tid & 127;
    const int p1s = 4 + (tid >> 7), p1n = tid & 127;
    const int u2s = tid >> 6, u2n = tid & 63;

    const float* xp0 = g_xw1 + (qbase * T_LEN) * (long)G1 + j;
    const float* U1j = U1 + j;
    const float  bb  = sb1[j];
    const u64t   b2p = pack2(sb2[j2], sb2[j2]);

    for (int t = 0; t < T_LEN; t++) {
        // ---------- Phase A: z1 = (h1 @ U1) + xw1_t + b1 ----------
        // xw1 DRAM loads issued first, independent of the matvec chain.
        const float* xp = xp0 + (long)t * G1;
        float xv[8];
        #pragma unroll
        for (int s = 0; s < 8; s++) xv[s] = xp[(long)s * T_LEN * G1];

        u64t a01 = 0ull, a23 = 0ull, a45 = 0ull, a67 = 0ull;

        #pragma unroll 1
        for (int kb = 0; kb < H1; kb += 16) {
            float u[16];
            #pragma unroll
            for (int i = 0; i < 16; i++) u[i] = U1j[(kb + i) * G1];
            #pragma unroll
            for (int i = 0; i < 16; i++) {
                ulonglong2 hA = *(const ulonglong2*)&h1T[(kb + i) * 8];
                ulonglong2 hB = *(const ulonglong2*)&h1T[(kb + i) * 8 + 4];
                u64t uu = pack2(u[i], u[i]);
                a01 = ffma2p(hA.x, uu, a01);
                a23 = ffma2p(hA.y, uu, a23);
                a45 = ffma2p(hB.x, uu, a45);
                a67 = ffma2p(hB.y, uu, a67);
            }
        }
        {
            float z0, z1, z2, z3, z4, z5, z6, z7;
            unpack2(a01, z0, z1); unpack2(a23, z2, z3);
            unpack2(a45, z4, z5); unpack2(a67, z6, z7);
            zbuf[0 * G1 + j] = z0 + xv[0] + bb;
            zbuf[1 * G1 + j] = z1 + xv[1] + bb;
            zbuf[2 * G1 + j] = z2 + xv[2] + bb;
            zbuf[3 * G1 + j] = z3 + xv[3] + bb;
            zbuf[4 * G1 + j] = z4 + xv[4] + bb;
            zbuf[5 * G1 + j] = z5 + xv[5] + bb;
            zbuf[6 * G1 + j] = z6 + xv[6] + bb;
            zbuf[7 * G1 + j] = z7 + xv[7] + bb;
        }
        __syncthreads();

        // ---------- LSTM1 update (2 states per thread) ----------
        {
            const float* zb = &zbuf[p0s * G1];
            float zi = zb[p0n], zf = zb[128 + p0n], zg = zb[256 + p0n], zo = zb[384 + p0n];
            c1a = fsig(zf) * c1a + fsig(zi) * tanh_ap(zg);
            h1T[p0n * 8 + p0s] = fsig(zo) * tanh_ap(c1a);
        }
        {
            const float* zb = &zbuf[p1s * G1];
            float zi = zb[p1n], zf = zb[128 + p1n], zg = zb[256 + p1n], zo = zb[384 + p1n];
            c1b = fsig(zf) * c1b + fsig(zi) * tanh_ap(zg);
            h1T[p1n * 8 + p1s] = fsig(zo) * tanh_ap(c1b);
        }
        __syncthreads();

        // ---------- Phase B: z2 = b2 + h1 @ W2 + h2 @ U2 ----------
        u64t a2a = b2p, a2b = b2p;

        #pragma unroll 8
        for (int k = 0; k < H1; k++) {
            ulonglong2 hv = *(const ulonglong2*)&h1T[k * 8 + s0];
            float wv = sW2[k * G2 + j2];
            u64t ww = pack2(wv, wv);
            a2a = ffma2p(hv.x, ww, a2a);
            a2b = ffma2p(hv.y, ww, a2b);
        }
        #pragma unroll 8
        for (int k = 0; k < H2; k++) {
            ulonglong2 hv = *(const ulonglong2*)&h2T[k * 8 + s0];
            float uv = sU2[k * G2 + j2];
            u64t uu = pack2(uv, uv);
            a2a = ffma2p(hv.x, uu, a2a);
            a2b = ffma2p(hv.y, uu, a2b);
        }
        {
            float y0, y1, y2, y3;
            unpack2(a2a, y0, y1); unpack2(a2b, y2, y3);
            zbuf[(s0 + 0) * G2 + j2] = y0;
            zbuf[(s0 + 1) * G2 + j2] = y1;
            zbuf[(s0 + 2) * G2 + j2] = y2;
            zbuf[(s0 + 3) * G2 + j2] = y3;
        }
        __syncthreads();

        // ---------- LSTM2 update ----------
        {
            const float* zb = &zbuf[u2s * G2];
            float zi = zb[u2n], zf = zb[64 + u2n], zg = zb[128 + u2n], zo = zb[192 + u2n];
            c2 = fsig(zf) * c2 + fsig(zi) * tanh_ap(zg);
            h2T[u2n * 8 + u2s] = fsig(zo) * tanh_ap(c2);
        }
        __syncthreads();
    }

    g_enc[(qbase + u2s) * H2 + u2n] = h2T[u2n * 8 + u2s];
}

// =====================================================================
// Kernel 3: heads (unchanged)
// =====================================================================
__global__ __launch_bounds__(128) void head_kernel(
    int encBase, int groupPerBatch,
    const float* __restrict__ W, const float* __restrict__ b,
    const float* __restrict__ g, const float* __restrict__ beta,
    const float* __restrict__ m, const float* __restrict__ v,
    float* __restrict__ out)
{
    __shared__ float x[128];
    const int row = blockIdx.x;
    const int tid = threadIdx.x;
    const int bidx = row / groupPerBatch;

    if (tid < 64) x[tid] = g_enc[(encBase + row) * H2 + tid];
    else          x[tid] = g_enc[(912 + bidx) * H2 + (tid - 64)];
    __syncthreads();

    if (tid < 32) {
        float acc = b[tid];
        #pragma unroll 8
        for (int k = 0; k < 128; k++) acc = fmaf(x[k], W[k * 32 + tid], acc);
        float y = fmaxf(acc, 0.0f);
        out[row * 32 + tid] = g[tid] * (y - m[tid]) * rsqrtf(v[tid] + 1e-3f) + beta[tid];
    }
}

// =====================================================================
extern "C" void kernel_launch(void* const* d_in, const int* in_sizes, int n_in,
                              void* d_out, int out_size)
{
    (void)in_sizes; (void)n_in; (void)out_size;

    const float* support = (const float*)d_in[0];
    const float* query   = (const float*)d_in[1];
    const float* unlabel = (const float*)d_in[2];
    const float* model   = (const float*)d_in[3];
    const float* W1 = (const float*)d_in[4];
    const float* U1 = (const float*)d_in[5];
    const float* b1 = (const float*)d_in[6];
    const float* W2 = (const float*)d_in[7];
    const float* U2 = (const float*)d_in[8];
    const float* b2 = (const float*)d_in[9];
    float* out = (float*)d_out;

    cudaFuncSetAttribute(gemm1_kernel,
                         cudaFuncAttributeMaxDynamicSharedMemorySize,
                         GEMM_SMEM_BYTES);
    dim3 ggrid(G1 / BN, MROWS / BM);   // (4, 920)
    gemm1_kernel<<<ggrid, 256, GEMM_SMEM_BYTES>>>(support, query, unlabel, model, W1);

    cudaFuncSetAttribute(lstm_kernel,
                         cudaFuncAttributeMaxDynamicSharedMemorySize,
                         LSTM_SMEM_BYTES);
    lstm_kernel<<<NSEQ / SEQ_PER_BLOCK, LSTM_THREADS, LSTM_SMEM_BYTES>>>(
        U1, b1, W2, U2, b2);

    head_kernel<<<200, 128>>>(0, 25,
        (const float*)d_in[10], (const float*)d_in[11], (const float*)d_in[12],
        (const float*)d_in[13], (const float*)d_in[14], (const float*)d_in[15],
        out);
    head_kernel<<<200, 128>>>(200, 25,
        (const float*)d_in[16], (const float*)d_in[17], (const float*)d_in[18],
        (const float*)d_in[19], (const float*)d_in[20], (const float*)d_in[21],
        out + 200 * 32);
    head_kernel<<<512, 128>>>(400, 64,
        (const float*)d_in[22], (const float*)d_in[23], (const float*)d_in[24],
        (const float*)d_in[25], (const float*)d_in[26], (const float*)d_in[27],
        out + 400 * 32);
}

// round 8
// speedup vs baseline: 1.6617x; 1.0359x over previous
#include <cuda_runtime.h>
#include <cuda_bf16.h>
#include <mma.h>
#include <cstdint>

using namespace nvcuda;

// ---------------- problem constants ----------------
#define T_LEN   128
#define E_DIM   768
#define H1      128
#define H2      64
#define G1      512   // 4*H1
#define G2      256   // 4*H2
#define NSEQ    920
#define MROWS   (NSEQ * T_LEN)   // 117760
#define SEQ_PER_BLOCK 8
#define LSTM_THREADS  512

#define ROW_SUP_END 25600
#define ROW_QRY_END 51200
#define ROW_UNL_END 116736

// ---------------- scratch ----------------
__device__ float g_xw1[(long)MROWS * G1];   // 241 MB
__device__ float g_enc[NSEQ * H2];

// ---------------- helpers ----------------
typedef unsigned long long u64t;

__device__ __forceinline__ float tanh_ap(float x) {
    float y; asm("tanh.approx.f32 %0, %1;" : "=f"(y) : "f"(x)); return y;
}
__device__ __forceinline__ float fsig(float x) {
    return fmaf(tanh_ap(0.5f * x), 0.5f, 0.5f);
}
__device__ __forceinline__ u64t ffma2p(u64t a, u64t b, u64t c) {
    u64t d;
    asm("fma.rn.f32x2 %0, %1, %2, %3;" : "=l"(d) : "l"(a), "l"(b), "l"(c));
    return d;
}
__device__ __forceinline__ u64t pack2(float x, float y) {
    u64t d; asm("mov.b64 %0, {%1, %2};" : "=l"(d) : "f"(x), "f"(y)); return d;
}
__device__ __forceinline__ void unpack2(u64t v, float& x, float& y) {
    asm("mov.b64 {%0, %1}, %2;" : "=f"(x), "=f"(y) : "l"(v));
}
__device__ __forceinline__ void cp16(void* smemDst, const void* gmemSrc) {
    unsigned sa = (unsigned)__cvta_generic_to_shared(smemDst);
    asm volatile("cp.async.cg.shared.global [%0], [%1], 16;\n" :: "r"(sa), "l"(gmemSrc));
}
#define CP_COMMIT() asm volatile("cp.async.commit_group;\n" ::)

// =====================================================================
// Kernel 1: xw1 = X @ W1. tf32 WMMA, CTA tile 128x128, BK=32,
// 3-stage cp.async pipeline (lookahead 2). 256 threads = 8 warps
// (4M x 2N), warp tile 32x64. NO explicit tf32 cvt (HMMA truncates).
// =====================================================================
#define BM 128
#define BN 128
#define BK 32
#define ASTRIDE 40
#define BSTRIDE 136
#define STAGE_FLOATS (BM*ASTRIDE + BK*BSTRIDE)           // 9472
#define GEMM_SMEM_FLOATS (3 * STAGE_FLOATS)              // 28416
#define GEMM_SMEM_BYTES  (GEMM_SMEM_FLOATS * 4)          // 113664

__global__ __launch_bounds__(256, 2) void gemm1_kernel(
    const float* __restrict__ support,
    const float* __restrict__ query,
    const float* __restrict__ unlabel,
    const float* __restrict__ model,
    const float* __restrict__ W1)
{
    extern __shared__ float gsm[];

    const int bn = blockIdx.x;             // 0..3
    const int bm = blockIdx.y;             // 0..919
    const long row0 = (long)bm * BM;

    const float* A;
    long arow;
    if (row0 < ROW_SUP_END)      { A = support; arow = row0; }
    else if (row0 < ROW_QRY_END) { A = query;   arow = row0 - ROW_SUP_END; }
    else if (row0 < ROW_UNL_END) { A = unlabel; arow = row0 - ROW_QRY_END; }
    else                         { A = model;   arow = row0 - ROW_UNL_END; }
    const float* Abase = A + arow * E_DIM;

    const int tid  = threadIdx.x;
    const int warp = tid >> 5;
    const int wm   = warp & 3;    // 32-row slice
    const int wn   = warp >> 2;   // 64-col slice

    wmma::fragment<wmma::accumulator, 16, 16, 8, float> cf[2][4];
    #pragma unroll
    for (int i = 0; i < 2; i++)
        #pragma unroll
        for (int jj = 0; jj < 4; jj++)
            wmma::fill_fragment(cf[i][jj], 0.0f);

    auto load_stage = [&](int st, int k0) {
        float* Ad = gsm + st * STAGE_FLOATS;
        float* Bd = Ad + BM * ASTRIDE;
        #pragma unroll
        for (int i = 0; i < 4; i++) {              // A: 1024 f4 slots
            int idx = tid + i * 256;
            int r = idx >> 3, c = (idx & 7) * 4;
            cp16(&Ad[r * ASTRIDE + c], Abase + (long)r * E_DIM + k0 + c);
        }
        #pragma unroll
        for (int i = 0; i < 4; i++) {              // B: 1024 f4 slots
            int idx = tid + i * 256;
            int r = idx >> 5, c = (idx & 31) * 4;
            cp16(&Bd[r * BSTRIDE + c], W1 + (long)(k0 + r) * G1 + bn * BN + c);
        }
        CP_COMMIT();
    };

    load_stage(0, 0);
    load_stage(1, BK);

    const int NKT = E_DIM / BK;   // 24
    int st = 0;
    for (int kt = 0; kt < NKT; kt++) {
        if (kt + 2 < NKT) {
            int st2 = st + 2; if (st2 >= 3) st2 -= 3;
            load_stage(st2, (kt + 2) * BK);
            asm volatile("cp.async.wait_group 2;\n" ::);
        } else {
            asm volatile("cp.async.wait_group 0;\n" ::);
        }
        __syncthreads();

        const float* Ac = gsm + st * STAGE_FLOATS;
        const float* Bc = Ac + BM * ASTRIDE;
        #pragma unroll
        for (int kk = 0; kk < 4; kk++) {
            wmma::fragment<wmma::matrix_a, 16, 16, 8, wmma::precision::tf32, wmma::row_major> af[2];
            #pragma unroll
            for (int i = 0; i < 2; i++)
                wmma::load_matrix_sync(af[i], &Ac[(wm * 32 + i * 16) * ASTRIDE + kk * 8], ASTRIDE);
            #pragma unroll
            for (int jj = 0; jj < 4; jj++) {
                wmma::fragment<wmma::matrix_b, 16, 16, 8, wmma::precision::tf32, wmma::row_major> bf;
                wmma::load_matrix_sync(bf, &Bc[(kk * 8) * BSTRIDE + wn * 64 + jj * 16], BSTRIDE);
                #pragma unroll
                for (int i = 0; i < 2; i++)
                    wmma::mma_sync(cf[i][jj], af[i], bf, cf[i][jj]);
            }
        }
        __syncthreads();
        if (++st >= 3) st -= 3;
    }

    #pragma unroll
    for (int i = 0; i < 2; i++)
        #pragma unroll
        for (int jj = 0; jj < 4; jj++) {
            float* dst = &g_xw1[(row0 + wm * 32 + i * 16) * (long)G1 + bn * BN + wn * 64 + jj * 16];
            wmma::store_matrix_sync(dst, cf[i][jj], G1, wmma::mem_row_major);
        }
}

// =====================================================================
// Kernel 2: fused LSTM1+LSTM2 (unchanged from R6)
// =====================================================================
#define LSTM_SMEM_FLOATS 55552
#define LSTM_SMEM_BYTES  (LSTM_SMEM_FLOATS * 4)

__global__ __launch_bounds__(LSTM_THREADS) void lstm_kernel(
    const float* __restrict__ U1,
    const float* __restrict__ b1,
    const float* __restrict__ W2,
    const float* __restrict__ U2,
    const float* __restrict__ b2)
{
    extern __shared__ float sm[];
    float* sW2  = sm;
    float* sU2  = sm + 32768;
    float* zbuf = sm + 49152;
    float* h1T  = sm + 53248;
    float* h2T  = sm + 54272;
    float* sb1  = sm + 54784;
    float* sb2  = sm + 55296;

    const int tid = threadIdx.x;
    const long qbase = (long)blockIdx.x * SEQ_PER_BLOCK;

    {
        const float4* s4 = (const float4*)W2;
        float4* d4 = (float4*)sW2;
        for (int i = tid; i < (H1 * G2) / 4; i += LSTM_THREADS) d4[i] = s4[i];
        s4 = (const float4*)U2; d4 = (float4*)sU2;
        for (int i = tid; i < (H2 * G2) / 4; i += LSTM_THREADS) d4[i] = s4[i];
        sb1[tid] = b1[tid];
        if (tid < G2) sb2[tid] = b2[tid];
        for (int i = tid; i < 128 * 8; i += LSTM_THREADS) h1T[i] = 0.0f;
        if (tid < 64 * 8) h2T[tid] = 0.0f;
    }
    __syncthreads();

    float c1a = 0.0f, c1b = 0.0f, c2 = 0.0f;

    const int j  = tid;
    const int j2 = tid & 255;
    const int s0 = (tid >> 8) * 4;

    const int p0s = tid >> 7, p0n = tid & 127;
    const int p1s = 4 + (tid >> 7), p1n = tid & 127;
    const int u2s = tid >> 6, u2n = tid & 63;

    const float* xp0 = g_xw1 + (qbase * T_LEN) * (long)G1 + j;
    const float* U1j = U1 + j;
    const float  bb  = sb1[j];
    const u64t   b2p = pack2(sb2[j2], sb2[j2]);

    for (int t = 0; t < T_LEN; t++) {
        // ---------- Phase A: z1 = (h1 @ U1) + xw1_t + b1 ----------
        const float* xp = xp0 + (long)t * G1;
        float xv[8];
        #pragma unroll
        for (int s = 0; s < 8; s++) xv[s] = xp[(long)s * T_LEN * G1];

        u64t a01 = 0ull, a23 = 0ull, a45 = 0ull, a67 = 0ull;

        #pragma unroll 1
        for (int kb = 0; kb < H1; kb += 16) {
            float u[16];
            #pragma unroll
            for (int i = 0; i < 16; i++) u[i] = U1j[(kb + i) * G1];
            #pragma unroll
            for (int i = 0; i < 16; i++) {
                ulonglong2 hA = *(const ulonglong2*)&h1T[(kb + i) * 8];
                ulonglong2 hB = *(const ulonglong2*)&h1T[(kb + i) * 8 + 4];
                u64t uu = pack2(u[i], u[i]);
                a01 = ffma2p(hA.x, uu, a01);
                a23 = ffma2p(hA.y, uu, a23);
                a45 = ffma2p(hB.x, uu, a45);
                a67 = ffma2p(hB.y, uu, a67);
            }
        }
        {
            float z0, z1, z2, z3, z4, z5, z6, z7;
            unpack2(a01, z0, z1); unpack2(a23, z2, z3);
            unpack2(a45, z4, z5); unpack2(a67, z6, z7);
            zbuf[0 * G1 + j] = z0 + xv[0] + bb;
            zbuf[1 * G1 + j] = z1 + xv[1] + bb;
            zbuf[2 * G1 + j] = z2 + xv[2] + bb;
            zbuf[3 * G1 + j] = z3 + xv[3] + bb;
            zbuf[4 * G1 + j] = z4 + xv[4] + bb;
            zbuf[5 * G1 + j] = z5 + xv[5] + bb;
            zbuf[6 * G1 + j] = z6 + xv[6] + bb;
            zbuf[7 * G1 + j] = z7 + xv[7] + bb;
        }
        __syncthreads();

        // ---------- LSTM1 update (2 states per thread) ----------
        {
            const float* zb = &zbuf[p0s * G1];
            float zi = zb[p0n], zf = zb[128 + p0n], zg = zb[256 + p0n], zo = zb[384 + p0n];
            c1a = fsig(zf) * c1a + fsig(zi) * tanh_ap(zg);
            h1T[p0n * 8 + p0s] = fsig(zo) * tanh_ap(c1a);
        }
        {
            const float* zb = &zbuf[p1s * G1];
            float zi = zb[p1n], zf = zb[128 + p1n], zg = zb[256 + p1n], zo = zb[384 + p1n];
            c1b = fsig(zf) * c1b + fsig(zi) * tanh_ap(zg);
            h1T[p1n * 8 + p1s] = fsig(zo) * tanh_ap(c1b);
        }
        __syncthreads();

        // ---------- Phase B: z2 = b2 + h1 @ W2 + h2 @ U2 ----------
        u64t a2a = b2p, a2b = b2p;

        #pragma unroll 8
        for (int k = 0; k < H1; k++) {
            ulonglong2 hv = *(const ulonglong2*)&h1T[k * 8 + s0];
            float wv = sW2[k * G2 + j2];
            u64t ww = pack2(wv, wv);
            a2a = ffma2p(hv.x, ww, a2a);
            a2b = ffma2p(hv.y, ww, a2b);
        }
        #pragma unroll 8
        for (int k = 0; k < H2; k++) {
            ulonglong2 hv = *(const ulonglong2*)&h2T[k * 8 + s0];
            float uv = sU2[k * G2 + j2];
            u64t uu = pack2(uv, uv);
            a2a = ffma2p(hv.x, uu, a2a);
            a2b = ffma2p(hv.y, uu, a2b);
        }
        {
            float y0, y1, y2, y3;
            unpack2(a2a, y0, y1); unpack2(a2b, y2, y3);
            zbuf[(s0 + 0) * G2 + j2] = y0;
            zbuf[(s0 + 1) * G2 + j2] = y1;
            zbuf[(s0 + 2) * G2 + j2] = y2;
            zbuf[(s0 + 3) * G2 + j2] = y3;
        }
        __syncthreads();

        // ---------- LSTM2 update ----------
        {
            const float* zb = &zbuf[u2s * G2];
            float zi = zb[u2n], zf = zb[64 + u2n], zg = zb[128 + u2n], zo = zb[192 + u2n];
            c2 = fsig(zf) * c2 + fsig(zi) * tanh_ap(zg);
            h2T[u2n * 8 + u2s] = fsig(zo) * tanh_ap(c2);
        }
        __syncthreads();
    }

    g_enc[(qbase + u2s) * H2 + u2n] = h2T[u2n * 8 + u2s];
}

// =====================================================================
// Kernel 3: ALL heads in one launch. 912 blocks; block -> segment.
// =====================================================================
__global__ __launch_bounds__(128) void heads_kernel(
    const float* __restrict__ W1h, const float* __restrict__ b1h,
    const float* __restrict__ g1h, const float* __restrict__ be1,
    const float* __restrict__ m1h, const float* __restrict__ v1h,
    const float* __restrict__ W2h, const float* __restrict__ b2h,
    const float* __restrict__ g2h, const float* __restrict__ be2,
    const float* __restrict__ m2h, const float* __restrict__ v2h,
    const float* __restrict__ W3h, const float* __restrict__ b3h,
    const float* __restrict__ g3h, const float* __restrict__ be3,
    const float* __restrict__ m3h, const float* __restrict__ v3h,
    float* __restrict__ out)
{
    __shared__ float x[128];
    const int row = blockIdx.x;       // 0..911 == enc row
    const int tid = threadIdx.x;

    const float *W, *b, *g, *beta, *m, *v;
    int bidx;
    if (row < 200)      { W = W1h; b = b1h; g = g1h; beta = be1; m = m1h; v = v1h; bidx = row / 25; }
    else if (row < 400) { W = W2h; b = b2h; g = g2h; beta = be2; m = m2h; v = v2h; bidx = (row - 200) / 25; }
    else                { W = W3h; b = b3h; g = g3h; beta = be3; m = m3h; v = v3h; bidx = (row - 400) / 64; }

    if (tid < 64) x[tid] = g_enc[row * H2 + tid];
    else          x[tid] = g_enc[(912 + bidx) * H2 + (tid - 64)];
    __syncthreads();

    if (tid < 32) {
        float acc = b[tid];
        #pragma unroll 8
        for (int k = 0; k < 128; k++) acc = fmaf(x[k], W[k * 32 + tid], acc);
        float y = fmaxf(acc, 0.0f);
        out[row * 32 + tid] = g[tid] * (y - m[tid]) * rsqrtf(v[tid] + 1e-3f) + beta[tid];
    }
}

// =====================================================================
extern "C" void kernel_launch(void* const* d_in, const int* in_sizes, int n_in,
                              void* d_out, int out_size)
{
    (void)in_sizes; (void)n_in; (void)out_size;

    const float* support = (const float*)d_in[0];
    const float* query   = (const float*)d_in[1];
    const float* unlabel = (const float*)d_in[2];
    const float* model   = (const float*)d_in[3];
    const float* W1 = (const float*)d_in[4];
    const float* U1 = (const float*)d_in[5];
    const float* b1 = (const float*)d_in[6];
    const float* W2 = (const float*)d_in[7];
    const float* U2 = (const float*)d_in[8];
    const float* b2 = (const float*)d_in[9];
    float* out = (float*)d_out;

    cudaFuncSetAttribute(gemm1_kernel,
                         cudaFuncAttributeMaxDynamicSharedMemorySize,
                         GEMM_SMEM_BYTES);
    dim3 ggrid(G1 / BN, MROWS / BM);   // (4, 920)
    gemm1_kernel<<<ggrid, 256, GEMM_SMEM_BYTES>>>(support, query, unlabel, model, W1);

    cudaFuncSetAttribute(lstm_kernel,
                         cudaFuncAttributeMaxDynamicSharedMemorySize,
                         LSTM_SMEM_BYTES);
    lstm_kernel<<<NSEQ / SEQ_PER_BLOCK, LSTM_THREADS, LSTM_SMEM_BYTES>>>(
        U1, b1, W2, U2, b2);

    heads_kernel<<<912, 128>>>(
        (const float*)d_in[10], (const float*)d_in[11], (const float*)d_in[12],
        (const float*)d_in[13], (const float*)d_in[14], (const float*)d_in[15],
        (const float*)d_in[16], (const float*)d_in[17], (const float*)d_in[18],
        (const float*)d_in[19], (const float*)d_in[20], (const float*)d_in[21],
        (const float*)d_in[22], (const float*)d_in[23], (const float*)d_in[24],
        (const float*)d_in[25], (const float*)d_in[26], (const float*)d_in[27],
        out);
}

// round 9
// speedup vs baseline: 1.6666x; 1.0029x over previous
#include <cuda_runtime.h>
#include <cuda_bf16.h>
#include <mma.h>
#include <cstdint>

using namespace nvcuda;

// ---------------- problem constants ----------------
#define T_LEN   128
#define E_DIM   768
#define H1      128
#define H2      64
#define G1      512   // 4*H1
#define G2      256   // 4*H2
#define NSEQ    920
#define MROWS   (NSEQ * T_LEN)   // 117760
#define SEQ_PER_BLOCK 8
#define LSTM_THREADS  512

#define ROW_SUP_END 25600
#define ROW_QRY_END 51200
#define ROW_UNL_END 116736

// ---------------- scratch ----------------
__device__ float g_xw1[(long)MROWS * G1];   // 241 MB
__device__ float g_enc[NSEQ * H2];

// ---------------- helpers ----------------
typedef unsigned long long u64t;

__device__ __forceinline__ float tanh_ap(float x) {
    float y; asm("tanh.approx.f32 %0, %1;" : "=f"(y) : "f"(x)); return y;
}
__device__ __forceinline__ float fsig(float x) {
    return fmaf(tanh_ap(0.5f * x), 0.5f, 0.5f);
}
__device__ __forceinline__ u64t ffma2p(u64t a, u64t b, u64t c) {
    u64t d;
    asm("fma.rn.f32x2 %0, %1, %2, %3;" : "=l"(d) : "l"(a), "l"(b), "l"(c));
    return d;
}
__device__ __forceinline__ u64t pack2(float x, float y) {
    u64t d; asm("mov.b64 %0, {%1, %2};" : "=l"(d) : "f"(x), "f"(y)); return d;
}
__device__ __forceinline__ void unpack2(u64t v, float& x, float& y) {
    asm("mov.b64 {%0, %1}, %2;" : "=f"(x), "=f"(y) : "l"(v));
}
__device__ __forceinline__ void cp16(void* smemDst, const void* gmemSrc) {
    unsigned sa = (unsigned)__cvta_generic_to_shared(smemDst);
    asm volatile("cp.async.cg.shared.global [%0], [%1], 16;\n" :: "r"(sa), "l"(gmemSrc));
}
#define CP_COMMIT() asm volatile("cp.async.commit_group;\n" ::)

// =====================================================================
// Kernel 1: xw1 = X @ W1. tf32 WMMA, CTA tile 128x128, BK=32,
// 3-stage cp.async, SINGLE __syncthreads per K-tile (cutlass-style
// multistage: wait -> sync -> prefetch(kt+2) -> compute(kt)).
// 256 threads = 8 warps (4M x 2N), warp tile 32x64, 2 CTAs/SM.
// =====================================================================
#define BM 128
#define BN 128
#define BK 32
#define ASTRIDE 40
#define BSTRIDE 136
#define STAGE_FLOATS (BM*ASTRIDE + BK*BSTRIDE)           // 9472
#define GEMM_SMEM_FLOATS (3 * STAGE_FLOATS)              // 28416
#define GEMM_SMEM_BYTES  (GEMM_SMEM_FLOATS * 4)          // 113664

__global__ __launch_bounds__(256, 2) void gemm1_kernel(
    const float* __restrict__ support,
    const float* __restrict__ query,
    const float* __restrict__ unlabel,
    const float* __restrict__ model,
    const float* __restrict__ W1)
{
    extern __shared__ float gsm[];

    const int bn = blockIdx.x;             // 0..3
    const int bm = blockIdx.y;             // 0..919
    const long row0 = (long)bm * BM;

    const float* A;
    long arow;
    if (row0 < ROW_SUP_END)      { A = support; arow = row0; }
    else if (row0 < ROW_QRY_END) { A = query;   arow = row0 - ROW_SUP_END; }
    else if (row0 < ROW_UNL_END) { A = unlabel; arow = row0 - ROW_QRY_END; }
    else                         { A = model;   arow = row0 - ROW_UNL_END; }
    const float* Abase = A + arow * E_DIM;

    const int tid  = threadIdx.x;
    const int warp = tid >> 5;
    const int wm   = warp & 3;    // 32-row slice
    const int wn   = warp >> 2;   // 64-col slice

    wmma::fragment<wmma::accumulator, 16, 16, 8, float> cf[2][4];
    #pragma unroll
    for (int i = 0; i < 2; i++)
        #pragma unroll
        for (int jj = 0; jj < 4; jj++)
            wmma::fill_fragment(cf[i][jj], 0.0f);

    auto load_stage = [&](int st, int k0) {
        float* Ad = gsm + st * STAGE_FLOATS;
        float* Bd = Ad + BM * ASTRIDE;
        #pragma unroll
        for (int i = 0; i < 4; i++) {              // A: 1024 f4 slots
            int idx = tid + i * 256;
            int r = idx >> 3, c = (idx & 7) * 4;
            cp16(&Ad[r * ASTRIDE + c], Abase + (long)r * E_DIM + k0 + c);
        }
        #pragma unroll
        for (int i = 0; i < 4; i++) {              // B: 1024 f4 slots
            int idx = tid + i * 256;
            int r = idx >> 5, c = (idx & 31) * 4;
            cp16(&Bd[r * BSTRIDE + c], W1 + (long)(k0 + r) * G1 + bn * BN + c);
        }
        CP_COMMIT();
    };

    load_stage(0, 0);
    load_stage(1, BK);

    const int NKT = E_DIM / BK;   // 24
    int st = 0;
    for (int kt = 0; kt < NKT; kt++) {
        // ensure stage kt's group is complete (groups retire in order)
        if (kt < NKT - 1) asm volatile("cp.async.wait_group 1;\n" ::);
        else              asm volatile("cp.async.wait_group 0;\n" ::);
        __syncthreads();   // ONE barrier per K-tile

        // prefetch two tiles ahead; target stage (st+2)%3 == (st-1)%3 was
        // fully consumed before the barrier above.
        if (kt + 2 < NKT) {
            int st2 = st + 2; if (st2 >= 3) st2 -= 3;
            load_stage(st2, (kt + 2) * BK);
        }

        const float* Ac = gsm + st * STAGE_FLOATS;
        const float* Bc = Ac + BM * ASTRIDE;
        #pragma unroll
        for (int kk = 0; kk < 4; kk++) {
            wmma::fragment<wmma::matrix_a, 16, 16, 8, wmma::precision::tf32, wmma::row_major> af[2];
            #pragma unroll
            for (int i = 0; i < 2; i++)
                wmma::load_matrix_sync(af[i], &Ac[(wm * 32 + i * 16) * ASTRIDE + kk * 8], ASTRIDE);
            #pragma unroll
            for (int jj = 0; jj < 4; jj++) {
                wmma::fragment<wmma::matrix_b, 16, 16, 8, wmma::precision::tf32, wmma::row_major> bf;
                wmma::load_matrix_sync(bf, &Bc[(kk * 8) * BSTRIDE + wn * 64 + jj * 16], BSTRIDE);
                #pragma unroll
                for (int i = 0; i < 2; i++)
                    wmma::mma_sync(cf[i][jj], af[i], bf, cf[i][jj]);
            }
        }
        if (++st >= 3) st -= 3;
    }

    #pragma unroll
    for (int i = 0; i < 2; i++)
        #pragma unroll
        for (int jj = 0; jj < 4; jj++) {
            float* dst = &g_xw1[(row0 + wm * 32 + i * 16) * (long)G1 + bn * BN + wn * 64 + jj * 16];
            wmma::store_matrix_sync(dst, cf[i][jj], G1, wmma::mem_row_major);
        }
}

// =====================================================================
// Kernel 2: fused LSTM1+LSTM2 (unchanged from R7/R8)
// =====================================================================
#define LSTM_SMEM_FLOATS 55552
#define LSTM_SMEM_BYTES  (LSTM_SMEM_FLOATS * 4)

__global__ __launch_bounds__(LSTM_THREADS) void lstm_kernel(
    const float* __restrict__ U1,
    const float* __restrict__ b1,
    const float* __restrict__ W2,
    const float* __restrict__ U2,
    const float* __restrict__ b2)
{
    extern __shared__ float sm[];
    float* sW2  = sm;
    float* sU2  = sm + 32768;
    float* zbuf = sm + 49152;
    float* h1T  = sm + 53248;
    float* h2T  = sm + 54272;
    float* sb1  = sm + 54784;
    float* sb2  = sm + 55296;

    const int tid = threadIdx.x;
    const long qbase = (long)blockIdx.x * SEQ_PER_BLOCK;

    {
        const float4* s4 = (const float4*)W2;
        float4* d4 = (float4*)sW2;
        for (int i = tid; i < (H1 * G2) / 4; i += LSTM_THREADS) d4[i] = s4[i];
        s4 = (const float4*)U2; d4 = (float4*)sU2;
        for (int i = tid; i < (H2 * G2) / 4; i += LSTM_THREADS) d4[i] = s4[i];
        sb1[tid] = b1[tid];
        if (tid < G2) sb2[tid] = b2[tid];
        for (int i = tid; i < 128 * 8; i += LSTM_THREADS) h1T[i] = 0.0f;
        if (tid < 64 * 8) h2T[tid] = 0.0f;
    }
    __syncthreads();

    float c1a = 0.0f, c1b = 0.0f, c2 = 0.0f;

    const int j  = tid;
    const int j2 = tid & 255;
    const int s0 = (tid >> 8) * 4;

    const int p0s = tid >> 7, p0n = tid & 127;
    const int p1s = 4 + (tid >> 7), p1n = tid & 127;
    const int u2s = tid >> 6, u2n = tid & 63;

    const float* xp0 = g_xw1 + (qbase * T_LEN) * (long)G1 + j;
    const float* U1j = U1 + j;
    const float  bb  = sb1[j];
    const u64t   b2p = pack2(sb2[j2], sb2[j2]);

    for (int t = 0; t < T_LEN; t++) {
        // ---------- Phase A: z1 = (h1 @ U1) + xw1_t + b1 ----------
        const float* xp = xp0 + (long)t * G1;
        float xv[8];
        #pragma unroll
        for (int s = 0; s < 8; s++) xv[s] = xp[(long)s * T_LEN * G1];

        u64t a01 = 0ull, a23 = 0ull, a45 = 0ull, a67 = 0ull;

        #pragma unroll 1
        for (int kb = 0; kb < H1; kb += 16) {
            float u[16];
            #pragma unroll
            for (int i = 0; i < 16; i++) u[i] = U1j[(kb + i) * G1];
            #pragma unroll
            for (int i = 0; i < 16; i++) {
                ulonglong2 hA = *(const ulonglong2*)&h1T[(kb + i) * 8];
                ulonglong2 hB = *(const ulonglong2*)&h1T[(kb + i) * 8 + 4];
                u64t uu = pack2(u[i], u[i]);
                a01 = ffma2p(hA.x, uu, a01);
                a23 = ffma2p(hA.y, uu, a23);
                a45 = ffma2p(hB.x, uu, a45);
                a67 = ffma2p(hB.y, uu, a67);
            }
        }
        {
            float z0, z1, z2, z3, z4, z5, z6, z7;
            unpack2(a01, z0, z1); unpack2(a23, z2, z3);
            unpack2(a45, z4, z5); unpack2(a67, z6, z7);
            zbuf[0 * G1 + j] = z0 + xv[0] + bb;
            zbuf[1 * G1 + j] = z1 + xv[1] + bb;
            zbuf[2 * G1 + j] = z2 + xv[2] + bb;
            zbuf[3 * G1 + j] = z3 + xv[3] + bb;
            zbuf[4 * G1 + j] = z4 + xv[4] + bb;
            zbuf[5 * G1 + j] = z5 + xv[5] + bb;
            zbuf[6 * G1 + j] = z6 + xv[6] + bb;
            zbuf[7 * G1 + j] = z7 + xv[7] + bb;
        }
        __syncthreads();

        // ---------- LSTM1 update (2 states per thread) ----------
        {
            const float* zb = &zbuf[p0s * G1];
            float zi = zb[p0n], zf = zb[128 + p0n], zg = zb[256 + p0n], zo = zb[384 + p0n];
            c1a = fsig(zf) * c1a + fsig(zi) * tanh_ap(zg);
            h1T[p0n * 8 + p0s] = fsig(zo) * tanh_ap(c1a);
        }
        {
            const float* zb = &zbuf[p1s * G1];
            float zi = zb[p1n], zf = zb[128 + p1n], zg = zb[256 + p1n], zo = zb[384 + p1n];
            c1b = fsig(zf) * c1b + fsig(zi) * tanh_ap(zg);
            h1T[p1n * 8 + p1s] = fsig(zo) * tanh_ap(c1b);
        }
        __syncthreads();

        // ---------- Phase B: z2 = b2 + h1 @ W2 + h2 @ U2 ----------
        u64t a2a = b2p, a2b = b2p;

        #pragma unroll 8
        for (int k = 0; k < H1; k++) {
            ulonglong2 hv = *(const ulonglong2*)&h1T[k * 8 + s0];
            float wv = sW2[k * G2 + j2];
            u64t ww = pack2(wv, wv);
            a2a = ffma2p(hv.x, ww, a2a);
            a2b = ffma2p(hv.y, ww, a2b);
        }
        #pragma unroll 8
        for (int k = 0; k < H2; k++) {
            ulonglong2 hv = *(const ulonglong2*)&h2T[k * 8 + s0];
            float uv = sU2[k * G2 + j2];
            u64t uu = pack2(uv, uv);
            a2a = ffma2p(hv.x, uu, a2a);
            a2b = ffma2p(hv.y, uu, a2b);
        }
        {
            float y0, y1, y2, y3;
            unpack2(a2a, y0, y1); unpack2(a2b, y2, y3);
            zbuf[(s0 + 0) * G2 + j2] = y0;
            zbuf[(s0 + 1) * G2 + j2] = y1;
            zbuf[(s0 + 2) * G2 + j2] = y2;
            zbuf[(s0 + 3) * G2 + j2] = y3;
        }
        __syncthreads();

        // ---------- LSTM2 update ----------
        {
            const float* zb = &zbuf[u2s * G2];
            float zi = zb[u2n], zf = zb[64 + u2n], zg = zb[128 + u2n], zo = zb[192 + u2n];
            c2 = fsig(zf) * c2 + fsig(zi) * tanh_ap(zg);
            h2T[u2n * 8 + u2s] = fsig(zo) * tanh_ap(c2);
        }
        __syncthreads();
    }

    g_enc[(qbase + u2s) * H2 + u2n] = h2T[u2n * 8 + u2s];
}

// =====================================================================
// Kernel 3: ALL heads in one launch (unchanged from R8)
// =====================================================================
__global__ __launch_bounds__(128) void heads_kernel(
    const float* __restrict__ W1h, const float* __restrict__ b1h,
    const float* __restrict__ g1h, const float* __restrict__ be1,
    const float* __restrict__ m1h, const float* __restrict__ v1h,
    const float* __restrict__ W2h, const float* __restrict__ b2h,
    const float* __restrict__ g2h, const float* __restrict__ be2,
    const float* __restrict__ m2h, const float* __restrict__ v2h,
    const float* __restrict__ W3h, const float* __restrict__ b3h,
    const float* __restrict__ g3h, const float* __restrict__ be3,
    const float* __restrict__ m3h, const float* __restrict__ v3h,
    float* __restrict__ out)
{
    __shared__ float x[128];
    const int row = blockIdx.x;       // 0..911 == enc row
    const int tid = threadIdx.x;

    const float *W, *b, *g, *beta, *m, *v;
    int bidx;
    if (row < 200)      { W = W1h; b = b1h; g = g1h; beta = be1; m = m1h; v = v1h; bidx = row / 25; }
    else if (row < 400) { W = W2h; b = b2h; g = g2h; beta = be2; m = m2h; v = v2h; bidx = (row - 200) / 25; }
    else                { W = W3h; b = b3h; g = g3h; beta = be3; m = m3h; v = v3h; bidx = (row - 400) / 64; }

    if (tid < 64) x[tid] = g_enc[row * H2 + tid];
    else          x[tid] = g_enc[(912 + bidx) * H2 + (tid - 64)];
    __syncthreads();

    if (tid < 32) {
        float acc = b[tid];
        #pragma unroll 8
        for (int k = 0; k < 128; k++) acc = fmaf(x[k], W[k * 32 + tid], acc);
        float y = fmaxf(acc, 0.0f);
        out[row * 32 + tid] = g[tid] * (y - m[tid]) * rsqrtf(v[tid] + 1e-3f) + beta[tid];
    }
}

// =====================================================================
extern "C" void kernel_launch(void* const* d_in, const int* in_sizes, int n_in,
                              void* d_out, int out_size)
{
    (void)in_sizes; (void)n_in; (void)out_size;

    const float* support = (const float*)d_in[0];
    const float* query   = (const float*)d_in[1];
    const float* unlabel = (const float*)d_in[2];
    const float* model   = (const float*)d_in[3];
    const float* W1 = (const float*)d_in[4];
    const float* U1 = (const float*)d_in[5];
    const float* b1 = (const float*)d_in[6];
    const float* W2 = (const float*)d_in[7];
    const float* U2 = (const float*)d_in[8];
    const float* b2 = (const float*)d_in[9];
    float* out = (float*)d_out;

    cudaFuncSetAttribute(gemm1_kernel,
                         cudaFuncAttributeMaxDynamicSharedMemorySize,
                         GEMM_SMEM_BYTES);
    dim3 ggrid(G1 / BN, MROWS / BM);   // (4, 920)
    gemm1_kernel<<<ggrid, 256, GEMM_SMEM_BYTES>>>(support, query, unlabel, model, W1);

    cudaFuncSetAttribute(lstm_kernel,
                         cudaFuncAttributeMaxDynamicSharedMemorySize,
                         LSTM_SMEM_BYTES);
    lstm_kernel<<<NSEQ / SEQ_PER_BLOCK, LSTM_THREADS, LSTM_SMEM_BYTES>>>(
        U1, b1, W2, U2, b2);

    heads_kernel<<<912, 128>>>(
        (const float*)d_in[10], (const float*)d_in[11], (const float*)d_in[12],
        (const float*)d_in[13], (const float*)d_in[14], (const float*)d_in[15],
        (const float*)d_in[16], (const float*)d_in[17], (const float*)d_in[18],
        (const float*)d_in[19], (const float*)d_in[20], (const float*)d_in[21],
        (const float*)d_in[22], (const float*)d_in[23], (const float*)d_in[24],
        (const float*)d_in[25], (const float*)d_in[26], (const float*)d_in[27],
        out);
}

// round 10
// speedup vs baseline: 1.6675x; 1.0005x over previous
#include <cuda_runtime.h>
#include <cuda_bf16.h>
#include <mma.h>
#include <cstdint>

using namespace nvcuda;

// ---------------- problem constants ----------------
#define T_LEN   128
#define E_DIM   768
#define H1      128
#define H2      64
#define G1      512   // 4*H1
#define G2      256   // 4*H2
#define NSEQ    920
#define MROWS   (NSEQ * T_LEN)   // 117760
#define SEQ_PER_BLOCK 8
#define LSTM_THREADS  512

#define ROW_SUP_END 25600
#define ROW_QRY_END 51200
#define ROW_UNL_END 116736

// ---------------- scratch ----------------
__device__ float g_xw1[(long)MROWS * G1];   // 241 MB
__device__ float g_enc[NSEQ * H2];

// ---------------- helpers ----------------
typedef unsigned long long u64t;

__device__ __forceinline__ float tanh_ap(float x) {
    float y; asm("tanh.approx.f32 %0, %1;" : "=f"(y) : "f"(x)); return y;
}
__device__ __forceinline__ float fsig(float x) {
    return fmaf(tanh_ap(0.5f * x), 0.5f, 0.5f);
}
__device__ __forceinline__ u64t ffma2p(u64t a, u64t b, u64t c) {
    u64t d;
    asm("fma.rn.f32x2 %0, %1, %2, %3;" : "=l"(d) : "l"(a), "l"(b), "l"(c));
    return d;
}
__device__ __forceinline__ u64t pack2(float x, float y) {
    u64t d; asm("mov.b64 %0, {%1, %2};" : "=l"(d) : "f"(x), "f"(y)); return d;
}
__device__ __forceinline__ void unpack2(u64t v, float& x, float& y) {
    asm("mov.b64 {%0, %1}, %2;" : "=f"(x), "=f"(y) : "l"(v));
}
__device__ __forceinline__ void cp16(void* smemDst, const void* gmemSrc) {
    unsigned sa = (unsigned)__cvta_generic_to_shared(smemDst);
    asm volatile("cp.async.cg.shared.global [%0], [%1], 16;\n" :: "r"(sa), "l"(gmemSrc));
}
#define CP_COMMIT() asm volatile("cp.async.commit_group;\n" ::)

// =====================================================================
// Kernel 1: xw1 = X @ W1. tf32 WMMA, CTA tile 128x128, BK=32,
// 3-stage cp.async, SINGLE __syncthreads per K-tile (cutlass-style
// multistage: wait -> sync -> prefetch(kt+2) -> compute(kt)).
// 256 threads = 8 warps (4M x 2N), warp tile 32x64, 2 CTAs/SM.
// =====================================================================
#define BM 128
#define BN 128
#define BK 32
#define ASTRIDE 40
#define BSTRIDE 136
#define STAGE_FLOATS (BM*ASTRIDE + BK*BSTRIDE)           // 9472
#define GEMM_SMEM_FLOATS (3 * STAGE_FLOATS)              // 28416
#define GEMM_SMEM_BYTES  (GEMM_SMEM_FLOATS * 4)          // 113664

__global__ __launch_bounds__(256, 2) void gemm1_kernel(
    const float* __restrict__ support,
    const float* __restrict__ query,
    const float* __restrict__ unlabel,
    const float* __restrict__ model,
    const float* __restrict__ W1)
{
    extern __shared__ float gsm[];

    const int bn = blockIdx.x;             // 0..3
    const int bm = blockIdx.y;             // 0..919
    const long row0 = (long)bm * BM;

    const float* A;
    long arow;
    if (row0 < ROW_SUP_END)      { A = support; arow = row0; }
    else if (row0 < ROW_QRY_END) { A = query;   arow = row0 - ROW_SUP_END; }
    else if (row0 < ROW_UNL_END) { A = unlabel; arow = row0 - ROW_QRY_END; }
    else                         { A = model;   arow = row0 - ROW_UNL_END; }
    const float* Abase = A + arow * E_DIM;

    const int tid  = threadIdx.x;
    const int warp = tid >> 5;
    const int wm   = warp & 3;    // 32-row slice
    const int wn   = warp >> 2;   // 64-col slice

    wmma::fragment<wmma::accumulator, 16, 16, 8, float> cf[2][4];
    #pragma unroll
    for (int i = 0; i < 2; i++)
        #pragma unroll
        for (int jj = 0; jj < 4; jj++)
            wmma::fill_fragment(cf[i][jj], 0.0f);

    auto load_stage = [&](int st, int k0) {
        float* Ad = gsm + st * STAGE_FLOATS;
        float* Bd = Ad + BM * ASTRIDE;
        #pragma unroll
        for (int i = 0; i < 4; i++) {              // A: 1024 f4 slots
            int idx = tid + i * 256;
            int r = idx >> 3, c = (idx & 7) * 4;
            cp16(&Ad[r * ASTRIDE + c], Abase + (long)r * E_DIM + k0 + c);
        }
        #pragma unroll
        for (int i = 0; i < 4; i++) {              // B: 1024 f4 slots
            int idx = tid + i * 256;
            int r = idx >> 5, c = (idx & 31) * 4;
            cp16(&Bd[r * BSTRIDE + c], W1 + (long)(k0 + r) * G1 + bn * BN + c);
        }
        CP_COMMIT();
    };

    load_stage(0, 0);
    load_stage(1, BK);

    const int NKT = E_DIM / BK;   // 24
    int st = 0;
    for (int kt = 0; kt < NKT; kt++) {
        // ensure stage kt's group is complete (groups retire in order)
        if (kt < NKT - 1) asm volatile("cp.async.wait_group 1;\n" ::);
        else              asm volatile("cp.async.wait_group 0;\n" ::);
        __syncthreads();   // ONE barrier per K-tile

        // prefetch two tiles ahead; target stage (st+2)%3 == (st-1)%3 was
        // fully consumed before the barrier above.
        if (kt + 2 < NKT) {
            int st2 = st + 2; if (st2 >= 3) st2 -= 3;
            load_stage(st2, (kt + 2) * BK);
        }

        const float* Ac = gsm + st * STAGE_FLOATS;
        const float* Bc = Ac + BM * ASTRIDE;
        #pragma unroll
        for (int kk = 0; kk < 4; kk++) {
            wmma::fragment<wmma::matrix_a, 16, 16, 8, wmma::precision::tf32, wmma::row_major> af[2];
            #pragma unroll
            for (int i = 0; i < 2; i++)
                wmma::load_matrix_sync(af[i], &Ac[(wm * 32 + i * 16) * ASTRIDE + kk * 8], ASTRIDE);
            #pragma unroll
            for (int jj = 0; jj < 4; jj++) {
                wmma::fragment<wmma::matrix_b, 16, 16, 8, wmma::precision::tf32, wmma::row_major> bf;
                wmma::load_matrix_sync(bf, &Bc[(kk * 8) * BSTRIDE + wn * 64 + jj * 16], BSTRIDE);
                #pragma unroll
                for (int i = 0; i < 2; i++)
                    wmma::mma_sync(cf[i][jj], af[i], bf, cf[i][jj]);
            }
        }
        if (++st >= 3) st -= 3;
    }

    #pragma unroll
    for (int i = 0; i < 2; i++)
        #pragma unroll
        for (int jj = 0; jj < 4; jj++) {
            float* dst = &g_xw1[(row0 + wm * 32 + i * 16) * (long)G1 + bn * BN + wn * 64 + jj * 16];
            wmma::store_matrix_sync(dst, cf[i][jj], G1, wmma::mem_row_major);
        }
}

// =====================================================================
// Kernel 2: fused LSTM1+LSTM2 (unchanged from R7/R8)
// =====================================================================
#define LSTM_SMEM_FLOATS 55552
#define LSTM_SMEM_BYTES  (LSTM_SMEM_FLOATS * 4)

__global__ __launch_bounds__(LSTM_THREADS) void lstm_kernel(
    const float* __restrict__ U1,
    const float* __restrict__ b1,
    const float* __restrict__ W2,
    const float* __restrict__ U2,
    const float* __restrict__ b2)
{
    extern __shared__ float sm[];
    float* sW2  = sm;
    float* sU2  = sm + 32768;
    float* zbuf = sm + 49152;
    float* h1T  = sm + 53248;
    float* h2T  = sm + 54272;
    float* sb1  = sm + 54784;
    float* sb2  = sm + 55296;

    const int tid = threadIdx.x;
    const long qbase = (long)blockIdx.x * SEQ_PER_BLOCK;

    {
        const float4* s4 = (const float4*)W2;
        float4* d4 = (float4*)sW2;
        for (int i = tid; i < (H1 * G2) / 4; i += LSTM_THREADS) d4[i] = s4[i];
        s4 = (const float4*)U2; d4 = (float4*)sU2;
        for (int i = tid; i < (H2 * G2) / 4; i += LSTM_THREADS) d4[i] = s4[i];
        sb1[tid] = b1[tid];
        if (tid < G2) sb2[tid] = b2[tid];
        for (int i = tid; i < 128 * 8; i += LSTM_THREADS) h1T[i] = 0.0f;
        if (tid < 64 * 8) h2T[tid] = 0.0f;
    }
    __syncthreads();

    float c1a = 0.0f, c1b = 0.0f, c2 = 0.0f;

    const int j  = tid;
    const int j2 = tid & 255;
    const int s0 = (tid >> 8) * 4;

    const int p0s = tid >> 7, p0n = tid & 127;
    const int p1s = 4 + (tid >> 7), p1n = tid & 127;
    const int u2s = tid >> 6, u2n = tid & 63;

    const float* xp0 = g_xw1 + (qbase * T_LEN) * (long)G1 + j;
    const float* U1j = U1 + j;
    const float  bb  = sb1[j];
    const u64t   b2p = pack2(sb2[j2], sb2[j2]);

    for (int t = 0; t < T_LEN; t++) {
        // ---------- Phase A: z1 = (h1 @ U1) + xw1_t + b1 ----------
        const float* xp = xp0 + (long)t * G1;
        float xv[8];
        #pragma unroll
        for (int s = 0; s < 8; s++) xv[s] = xp[(long)s * T_LEN * G1];

        u64t a01 = 0ull, a23 = 0ull, a45 = 0ull, a67 = 0ull;

        #pragma unroll 1
        for (int kb = 0; kb < H1; kb += 16) {
            float u[16];
            #pragma unroll
            for (int i = 0; i < 16; i++) u[i] = U1j[(kb + i) * G1];
            #pragma unroll
            for (int i = 0; i < 16; i++) {
                ulonglong2 hA = *(const ulonglong2*)&h1T[(kb + i) * 8];
                ulonglong2 hB = *(const ulonglong2*)&h1T[(kb + i) * 8 + 4];
                u64t uu = pack2(u[i], u[i]);
                a01 = ffma2p(hA.x, uu, a01);
                a23 = ffma2p(hA.y, uu, a23);
                a45 = ffma2p(hB.x, uu, a45);
                a67 = ffma2p(hB.y, uu, a67);
            }
        }
        {
            float z0, z1, z2, z3, z4, z5, z6, z7;
            unpack2(a01, z0, z1); unpack2(a23, z2, z3);
            unpack2(a45, z4, z5); unpack2(a67, z6, z7);
            zbuf[0 * G1 + j] = z0 + xv[0] + bb;
            zbuf[1 * G1 + j] = z1 + xv[1] + bb;
            zbuf[2 * G1 + j] = z2 + xv[2] + bb;
            zbuf[3 * G1 + j] = z3 + xv[3] + bb;
            zbuf[4 * G1 + j] = z4 + xv[4] + bb;
            zbuf[5 * G1 + j] = z5 + xv[5] + bb;
            zbuf[6 * G1 + j] = z6 + xv[6] + bb;
            zbuf[7 * G1 + j] = z7 + xv[7] + bb;
        }
        __syncthreads();

        // ---------- LSTM1 update (2 states per thread) ----------
        {
            const float* zb = &zbuf[p0s * G1];
            float zi = zb[p0n], zf = zb[128 + p0n], zg = zb[256 + p0n], zo = zb[384 + p0n];
            c1a = fsig(zf) * c1a + fsig(zi) * tanh_ap(zg);
            h1T[p0n * 8 + p0s] = fsig(zo) * tanh_ap(c1a);
        }
        {
            const float* zb = &zbuf[p1s * G1];
            float zi = zb[p1n], zf = zb[128 + p1n], zg = zb[256 + p1n], zo = zb[384 + p1n];
            c1b = fsig(zf) * c1b + fsig(zi) * tanh_ap(zg);
            h1T[p1n * 8 + p1s] = fsig(zo) * tanh_ap(c1b);
        }
        __syncthreads();

        // ---------- Phase B: z2 = b2 + h1 @ W2 + h2 @ U2 ----------
        u64t a2a = b2p, a2b = b2p;

        #pragma unroll 8
        for (int k = 0; k < H1; k++) {
            ulonglong2 hv = *(const ulonglong2*)&h1T[k * 8 + s0];
            float wv = sW2[k * G2 + j2];
            u64t ww = pack2(wv, wv);
            a2a = ffma2p(hv.x, ww, a2a);
            a2b = ffma2p(hv.y, ww, a2b);
        }
        #pragma unroll 8
        for (int k = 0; k < H2; k++) {
            ulonglong2 hv = *(const ulonglong2*)&h2T[k * 8 + s0];
            float uv = sU2[k * G2 + j2];
            u64t uu = pack2(uv, uv);
            a2a = ffma2p(hv.x, uu, a2a);
            a2b = ffma2p(hv.y, uu, a2b);
        }
        {
            float y0, y1, y2, y3;
            unpack2(a2a, y0, y1); unpack2(a2b, y2, y3);
            zbuf[(s0 + 0) * G2 + j2] = y0;
            zbuf[(s0 + 1) * G2 + j2] = y1;
            zbuf[(s0 + 2) * G2 + j2] = y2;
            zbuf[(s0 + 3) * G2 + j2] = y3;
        }
        __syncthreads();

        // ---------- LSTM2 update ----------
        {
            const float* zb = &zbuf[u2s * G2];
            float zi = zb[u2n], zf = zb[64 + u2n], zg = zb[128 + u2n], zo = zb[192 + u2n];
            c2 = fsig(zf) * c2 + fsig(zi) * tanh_ap(zg);
            h2T[u2n * 8 + u2s] = fsig(zo) * tanh_ap(c2);
        }
        __syncthreads();
    }

    g_enc[(qbase + u2s) * H2 + u2n] = h2T[u2n * 8 + u2s];
}

// =====================================================================
// Kernel 3: ALL heads in one launch (unchanged from R8)
// =====================================================================
__global__ __launch_bounds__(128) void heads_kernel(
    const float* __restrict__ W1h, const float* __restrict__ b1h,
    const float* __restrict__ g1h, const float* __restrict__ be1,
    const float* __restrict__ m1h, const float* __restrict__ v1h,
    const float* __restrict__ W2h, const float* __restrict__ b2h,
    const float* __restrict__ g2h, const float* __restrict__ be2,
    const float* __restrict__ m2h, const float* __restrict__ v2h,
    const float* __restrict__ W3h, const float* __restrict__ b3h,
    const float* __restrict__ g3h, const float* __restrict__ be3,
    const float* __restrict__ m3h, const float* __restrict__ v3h,
    float* __restrict__ out)
{
    __shared__ float x[128];
    const int row = blockIdx.x;       // 0..911 == enc row
    const int tid = threadIdx.x;

    const float *W, *b, *g, *beta, *m, *v;
    int bidx;
    if (row < 200)      { W = W1h; b = b1h; g = g1h; beta = be1; m = m1h; v = v1h; bidx = row / 25; }
    else if (row < 400) { W = W2h; b = b2h; g = g2h; beta = be2; m = m2h; v = v2h; bidx = (row - 200) / 25; }
    else                { W = W3h; b = b3h; g = g3h; beta = be3; m = m3h; v = v3h; bidx = (row - 400) / 64; }

    if (tid < 64) x[tid] = g_enc[row * H2 + tid];
    else          x[tid] = g_enc[(912 + bidx) * H2 + (tid - 64)];
    __syncthreads();

    if (tid < 32) {
        float acc = b[tid];
        #pragma unroll 8
        for (int k = 0; k < 128; k++) acc = fmaf(x[k], W[k * 32 + tid], acc);
        float y = fmaxf(acc, 0.0f);
        out[row * 32 + tid] = g[tid] * (y - m[tid]) * rsqrtf(v[tid] + 1e-3f) + beta[tid];
    }
}

// =====================================================================
extern "C" void kernel_launch(void* const* d_in, const int* in_sizes, int n_in,
                              void* d_out, int out_size)
{
    (void)in_sizes; (void)n_in; (void)out_size;

    const float* support = (const float*)d_in[0];
    const float* query   = (const float*)d_in[1];
    const float* unlabel = (const float*)d_in[2];
    const float* model   = (const float*)d_in[3];
    const float* W1 = (const float*)d_in[4];
    const float* U1 = (const float*)d_in[5];
    const float* b1 = (const float*)d_in[6];
    const float* W2 = (const float*)d_in[7];
    const float* U2 = (const float*)d_in[8];
    const float* b2 = (const float*)d_in[9];
    float* out = (float*)d_out;

    cudaFuncSetAttribute(gemm1_kernel,
                         cudaFuncAttributeMaxDynamicSharedMemorySize,
                         GEMM_SMEM_BYTES);
    dim3 ggrid(G1 / BN, MROWS / BM);   // (4, 920)
    gemm1_kernel<<<ggrid, 256, GEMM_SMEM_BYTES>>>(support, query, unlabel, model, W1);

    cudaFuncSetAttribute(lstm_kernel,
                         cudaFuncAttributeMaxDynamicSharedMemorySize,
                         LSTM_SMEM_BYTES);
    lstm_kernel<<<NSEQ / SEQ_PER_BLOCK, LSTM_THREADS, LSTM_SMEM_BYTES>>>(
        U1, b1, W2, U2, b2);

    heads_kernel<<<912, 128>>>(
        (const float*)d_in[10], (const float*)d_in[11], (const float*)d_in[12],
        (const float*)d_in[13], (const float*)d_in[14], (const float*)d_in[15],
        (const float*)d_in[16], (const float*)d_in[17], (const float*)d_in[18],
        (const float*)d_in[19], (const float*)d_in[20], (const float*)d_in[21],
        (const float*)d_in[22], (const float*)d_in[23], (const float*)d_in[24],
        (const float*)d_in[25], (const float*)d_in[26], (const float*)d_in[27],
        out);
}

// round 11
// speedup vs baseline: 1.6676x; 1.0001x over previous
#include <cuda_runtime.h>
#include <cuda_bf16.h>
#include <mma.h>
#include <cstdint>

using namespace nvcuda;

// ---------------- problem constants ----------------
#define T_LEN   128
#define E_DIM   768
#define H1      128
#define H2      64
#define G1      512   // 4*H1
#define G2      256   // 4*H2
#define NSEQ    920
#define MROWS   (NSEQ * T_LEN)   // 117760
#define SEQ_PER_BLOCK 8
#define LSTM_THREADS  512

#define ROW_SUP_END 25600
#define ROW_QRY_END 51200
#define ROW_UNL_END 116736

// ---------------- scratch ----------------
__device__ float g_xw1[(long)MROWS * G1];   // 241 MB
__device__ float g_enc[NSEQ * H2];

// ---------------- helpers ----------------
typedef unsigned long long u64t;

__device__ __forceinline__ float tanh_ap(float x) {
    float y; asm("tanh.approx.f32 %0, %1;" : "=f"(y) : "f"(x)); return y;
}
__device__ __forceinline__ float fsig(float x) {
    return fmaf(tanh_ap(0.5f * x), 0.5f, 0.5f);
}
__device__ __forceinline__ u64t ffma2p(u64t a, u64t b, u64t c) {
    u64t d;
    asm("fma.rn.f32x2 %0, %1, %2, %3;" : "=l"(d) : "l"(a), "l"(b), "l"(c));
    return d;
}
__device__ __forceinline__ u64t pack2(float x, float y) {
    u64t d; asm("mov.b64 %0, {%1, %2};" : "=l"(d) : "f"(x), "f"(y)); return d;
}
__device__ __forceinline__ void unpack2(u64t v, float& x, float& y) {
    asm("mov.b64 {%0, %1}, %2;" : "=f"(x), "=f"(y) : "l"(v));
}
__device__ __forceinline__ void cp16(void* smemDst, const void* gmemSrc) {
    unsigned sa = (unsigned)__cvta_generic_to_shared(smemDst);
    asm volatile("cp.async.cg.shared.global [%0], [%1], 16;\n" :: "r"(sa), "l"(gmemSrc));
}
#define CP_COMMIT() asm volatile("cp.async.commit_group;\n" ::)

// =====================================================================
// Kernel 1: xw1 = X @ W1. tf32 WMMA, CTA tile 128x128, BK=32,
// 3-stage cp.async, SINGLE __syncthreads per K-tile (cutlass-style
// multistage: wait -> sync -> prefetch(kt+2) -> compute(kt)).
// 256 threads = 8 warps (4M x 2N), warp tile 32x64, 2 CTAs/SM.
// =====================================================================
#define BM 128
#define BN 128
#define BK 32
#define ASTRIDE 40
#define BSTRIDE 136
#define STAGE_FLOATS (BM*ASTRIDE + BK*BSTRIDE)           // 9472
#define GEMM_SMEM_FLOATS (3 * STAGE_FLOATS)              // 28416
#define GEMM_SMEM_BYTES  (GEMM_SMEM_FLOATS * 4)          // 113664

__global__ __launch_bounds__(256, 2) void gemm1_kernel(
    const float* __restrict__ support,
    const float* __restrict__ query,
    const float* __restrict__ unlabel,
    const float* __restrict__ model,
    const float* __restrict__ W1)
{
    extern __shared__ float gsm[];

    const int bn = blockIdx.x;             // 0..3
    const int bm = blockIdx.y;             // 0..919
    const long row0 = (long)bm * BM;

    const float* A;
    long arow;
    if (row0 < ROW_SUP_END)      { A = support; arow = row0; }
    else if (row0 < ROW_QRY_END) { A = query;   arow = row0 - ROW_SUP_END; }
    else if (row0 < ROW_UNL_END) { A = unlabel; arow = row0 - ROW_QRY_END; }
    else                         { A = model;   arow = row0 - ROW_UNL_END; }
    const float* Abase = A + arow * E_DIM;

    const int tid  = threadIdx.x;
    const int warp = tid >> 5;
    const int wm   = warp & 3;    // 32-row slice
    const int wn   = warp >> 2;   // 64-col slice

    wmma::fragment<wmma::accumulator, 16, 16, 8, float> cf[2][4];
    #pragma unroll
    for (int i = 0; i < 2; i++)
        #pragma unroll
        for (int jj = 0; jj < 4; jj++)
            wmma::fill_fragment(cf[i][jj], 0.0f);

    auto load_stage = [&](int st, int k0) {
        float* Ad = gsm + st * STAGE_FLOATS;
        float* Bd = Ad + BM * ASTRIDE;
        #pragma unroll
        for (int i = 0; i < 4; i++) {              // A: 1024 f4 slots
            int idx = tid + i * 256;
            int r = idx >> 3, c = (idx & 7) * 4;
            cp16(&Ad[r * ASTRIDE + c], Abase + (long)r * E_DIM + k0 + c);
        }
        #pragma unroll
        for (int i = 0; i < 4; i++) {              // B: 1024 f4 slots
            int idx = tid + i * 256;
            int r = idx >> 5, c = (idx & 31) * 4;
            cp16(&Bd[r * BSTRIDE + c], W1 + (long)(k0 + r) * G1 + bn * BN + c);
        }
        CP_COMMIT();
    };

    load_stage(0, 0);
    load_stage(1, BK);

    const int NKT = E_DIM / BK;   // 24
    int st = 0;
    for (int kt = 0; kt < NKT; kt++) {
        // ensure stage kt's group is complete (groups retire in order)
        if (kt < NKT - 1) asm volatile("cp.async.wait_group 1;\n" ::);
        else              asm volatile("cp.async.wait_group 0;\n" ::);
        __syncthreads();   // ONE barrier per K-tile

        // prefetch two tiles ahead; target stage (st+2)%3 == (st-1)%3 was
        // fully consumed before the barrier above.
        if (kt + 2 < NKT) {
            int st2 = st + 2; if (st2 >= 3) st2 -= 3;
            load_stage(st2, (kt + 2) * BK);
        }

        const float* Ac = gsm + st * STAGE_FLOATS;
        const float* Bc = Ac + BM * ASTRIDE;
        #pragma unroll
        for (int kk = 0; kk < 4; kk++) {
            wmma::fragment<wmma::matrix_a, 16, 16, 8, wmma::precision::tf32, wmma::row_major> af[2];
            #pragma unroll
            for (int i = 0; i < 2; i++)
                wmma::load_matrix_sync(af[i], &Ac[(wm * 32 + i * 16) * ASTRIDE + kk * 8], ASTRIDE);
            #pragma unroll
            for (int jj = 0; jj < 4; jj++) {
                wmma::fragment<wmma::matrix_b, 16, 16, 8, wmma::precision::tf32, wmma::row_major> bf;
                wmma::load_matrix_sync(bf, &Bc[(kk * 8) * BSTRIDE + wn * 64 + jj * 16], BSTRIDE);
                #pragma unroll
                for (int i = 0; i < 2; i++)
                    wmma::mma_sync(cf[i][jj], af[i], bf, cf[i][jj]);
            }
        }
        if (++st >= 3) st -= 3;
    }

    #pragma unroll
    for (int i = 0; i < 2; i++)
        #pragma unroll
        for (int jj = 0; jj < 4; jj++) {
            float* dst = &g_xw1[(row0 + wm * 32 + i * 16) * (long)G1 + bn * BN + wn * 64 + jj * 16];
            wmma::store_matrix_sync(dst, cf[i][jj], G1, wmma::mem_row_major);
        }
}

// =====================================================================
// Kernel 2: fused LSTM1+LSTM2 (unchanged from R7/R8)
// =====================================================================
#define LSTM_SMEM_FLOATS 55552
#define LSTM_SMEM_BYTES  (LSTM_SMEM_FLOATS * 4)

__global__ __launch_bounds__(LSTM_THREADS) void lstm_kernel(
    const float* __restrict__ U1,
    const float* __restrict__ b1,
    const float* __restrict__ W2,
    const float* __restrict__ U2,
    const float* __restrict__ b2)
{
    extern __shared__ float sm[];
    float* sW2  = sm;
    float* sU2  = sm + 32768;
    float* zbuf = sm + 49152;
    float* h1T  = sm + 53248;
    float* h2T  = sm + 54272;
    float* sb1  = sm + 54784;
    float* sb2  = sm + 55296;

    const int tid = threadIdx.x;
    const long qbase = (long)blockIdx.x * SEQ_PER_BLOCK;

    {
        const float4* s4 = (const float4*)W2;
        float4* d4 = (float4*)sW2;
        for (int i = tid; i < (H1 * G2) / 4; i += LSTM_THREADS) d4[i] = s4[i];
        s4 = (const float4*)U2; d4 = (float4*)sU2;
        for (int i = tid; i < (H2 * G2) / 4; i += LSTM_THREADS) d4[i] = s4[i];
        sb1[tid] = b1[tid];
        if (tid < G2) sb2[tid] = b2[tid];
        for (int i = tid; i < 128 * 8; i += LSTM_THREADS) h1T[i] = 0.0f;
        if (tid < 64 * 8) h2T[tid] = 0.0f;
    }
    __syncthreads();

    float c1a = 0.0f, c1b = 0.0f, c2 = 0.0f;

    const int j  = tid;
    const int j2 = tid & 255;
    const int s0 = (tid >> 8) * 4;

    const int p0s = tid >> 7, p0n = tid & 127;
    const int p1s = 4 + (tid >> 7), p1n = tid & 127;
    const int u2s = tid >> 6, u2n = tid & 63;

    const float* xp0 = g_xw1 + (qbase * T_LEN) * (long)G1 + j;
    const float* U1j = U1 + j;
    const float  bb  = sb1[j];
    const u64t   b2p = pack2(sb2[j2], sb2[j2]);

    for (int t = 0; t < T_LEN; t++) {
        // ---------- Phase A: z1 = (h1 @ U1) + xw1_t + b1 ----------
        const float* xp = xp0 + (long)t * G1;
        float xv[8];
        #pragma unroll
        for (int s = 0; s < 8; s++) xv[s] = xp[(long)s * T_LEN * G1];

        u64t a01 = 0ull, a23 = 0ull, a45 = 0ull, a67 = 0ull;

        #pragma unroll 1
        for (int kb = 0; kb < H1; kb += 16) {
            float u[16];
            #pragma unroll
            for (int i = 0; i < 16; i++) u[i] = U1j[(kb + i) * G1];
            #pragma unroll
            for (int i = 0; i < 16; i++) {
                ulonglong2 hA = *(const ulonglong2*)&h1T[(kb + i) * 8];
                ulonglong2 hB = *(const ulonglong2*)&h1T[(kb + i) * 8 + 4];
                u64t uu = pack2(u[i], u[i]);
                a01 = ffma2p(hA.x, uu, a01);
                a23 = ffma2p(hA.y, uu, a23);
                a45 = ffma2p(hB.x, uu, a45);
                a67 = ffma2p(hB.y, uu, a67);
            }
        }
        {
            float z0, z1, z2, z3, z4, z5, z6, z7;
            unpack2(a01, z0, z1); unpack2(a23, z2, z3);
            unpack2(a45, z4, z5); unpack2(a67, z6, z7);
            zbuf[0 * G1 + j] = z0 + xv[0] + bb;
            zbuf[1 * G1 + j] = z1 + xv[1] + bb;
            zbuf[2 * G1 + j] = z2 + xv[2] + bb;
            zbuf[3 * G1 + j] = z3 + xv[3] + bb;
            zbuf[4 * G1 + j] = z4 + xv[4] + bb;
            zbuf[5 * G1 + j] = z5 + xv[5] + bb;
            zbuf[6 * G1 + j] = z6 + xv[6] + bb;
            zbuf[7 * G1 + j] = z7 + xv[7] + bb;
        }
        __syncthreads();

        // ---------- LSTM1 update (2 states per thread) ----------
        {
            const float* zb = &zbuf[p0s * G1];
            float zi = zb[p0n], zf = zb[128 + p0n], zg = zb[256 + p0n], zo = zb[384 + p0n];
            c1a = fsig(zf) * c1a + fsig(zi) * tanh_ap(zg);
            h1T[p0n * 8 + p0s] = fsig(zo) * tanh_ap(c1a);
        }
        {
            const float* zb = &zbuf[p1s * G1];
            float zi = zb[p1n], zf = zb[128 + p1n], zg = zb[256 + p1n], zo = zb[384 + p1n];
            c1b = fsig(zf) * c1b + fsig(zi) * tanh_ap(zg);
            h1T[p1n * 8 + p1s] = fsig(zo) * tanh_ap(c1b);
        }
        __syncthreads();

        // ---------- Phase B: z2 = b2 + h1 @ W2 + h2 @ U2 ----------
        u64t a2a = b2p, a2b = b2p;

        #pragma unroll 8
        for (int k = 0; k < H1; k++) {
            ulonglong2 hv = *(const ulonglong2*)&h1T[k * 8 + s0];
            float wv = sW2[k * G2 + j2];
            u64t ww = pack2(wv, wv);
            a2a = ffma2p(hv.x, ww, a2a);
            a2b = ffma2p(hv.y, ww, a2b);
        }
        #pragma unroll 8
        for (int k = 0; k < H2; k++) {
            ulonglong2 hv = *(const ulonglong2*)&h2T[k * 8 + s0];
            float uv = sU2[k * G2 + j2];
            u64t uu = pack2(uv, uv);
            a2a = ffma2p(hv.x, uu, a2a);
            a2b = ffma2p(hv.y, uu, a2b);
        }
        {
            float y0, y1, y2, y3;
            unpack2(a2a, y0, y1); unpack2(a2b, y2, y3);
            zbuf[(s0 + 0) * G2 + j2] = y0;
            zbuf[(s0 + 1) * G2 + j2] = y1;
            zbuf[(s0 + 2) * G2 + j2] = y2;
            zbuf[(s0 + 3) * G2 + j2] = y3;
        }
        __syncthreads();

        // ---------- LSTM2 update ----------
        {
            const float* zb = &zbuf[u2s * G2];
            float zi = zb[u2n], zf = zb[64 + u2n], zg = zb[128 + u2n], zo = zb[192 + u2n];
            c2 = fsig(zf) * c2 + fsig(zi) * tanh_ap(zg);
            h2T[u2n * 8 + u2s] = fsig(zo) * tanh_ap(c2);
        }
        __syncthreads();
    }

    g_enc[(qbase + u2s) * H2 + u2n] = h2T[u2n * 8 + u2s];
}

// =====================================================================
// Kernel 3: ALL heads in one launch (unchanged from R8)
// =====================================================================
__global__ __launch_bounds__(128) void heads_kernel(
    const float* __restrict__ W1h, const float* __restrict__ b1h,
    const float* __restrict__ g1h, const float* __restrict__ be1,
    const float* __restrict__ m1h, const float* __restrict__ v1h,
    const float* __restrict__ W2h, const float* __restrict__ b2h,
    const float* __restrict__ g2h, const float* __restrict__ be2,
    const float* __restrict__ m2h, const float* __restrict__ v2h,
    const float* __restrict__ W3h, const float* __restrict__ b3h,
    const float* __restrict__ g3h, const float* __restrict__ be3,
    const float* __restrict__ m3h, const float* __restrict__ v3h,
    float* __restrict__ out)
{
    __shared__ float x[128];
    const int row = blockIdx.x;       // 0..911 == enc row
    const int tid = threadIdx.x;

    const float *W, *b, *g, *beta, *m, *v;
    int bidx;
    if (row < 200)      { W = W1h; b = b1h; g = g1h; beta = be1; m = m1h; v = v1h; bidx = row / 25; }
    else if (row < 400) { W = W2h; b = b2h; g = g2h; beta = be2; m = m2h; v = v2h; bidx = (row - 200) / 25; }
    else                { W = W3h; b = b3h; g = g3h; beta = be3; m = m3h; v = v3h; bidx = (row - 400) / 64; }

    if (tid < 64) x[tid] = g_enc[row * H2 + tid];
    else          x[tid] = g_enc[(912 + bidx) * H2 + (tid - 64)];
    __syncthreads();

    if (tid < 32) {
        float acc = b[tid];
        #pragma unroll 8
        for (int k = 0; k < 128; k++) acc = fmaf(x[k], W[k * 32 + tid], acc);
        float y = fmaxf(acc, 0.0f);
        out[row * 32 + tid] = g[tid] * (y - m[tid]) * rsqrtf(v[tid] + 1e-3f) + beta[tid];
    }
}

// =====================================================================
extern "C" void kernel_launch(void* const* d_in, const int* in_sizes, int n_in,
                              void* d_out, int out_size)
{
    (void)in_sizes; (void)n_in; (void)out_size;

    const float* support = (const float*)d_in[0];
    const float* query   = (const float*)d_in[1];
    const float* unlabel = (const float*)d_in[2];
    const float* model   = (const float*)d_in[3];
    const float* W1 = (const float*)d_in[4];
    const float* U1 = (const float*)d_in[5];
    const float* b1 = (const float*)d_in[6];
    const float* W2 = (const float*)d_in[7];
    const float* U2 = (const float*)d_in[8];
    const float* b2 = (const float*)d_in[9];
    float* out = (float*)d_out;

    cudaFuncSetAttribute(gemm1_kernel,
                         cudaFuncAttributeMaxDynamicSharedMemorySize,
                         GEMM_SMEM_BYTES);
    dim3 ggrid(G1 / BN, MROWS / BM);   // (4, 920)
    gemm1_kernel<<<ggrid, 256, GEMM_SMEM_BYTES>>>(support, query, unlabel, model, W1);

    cudaFuncSetAttribute(lstm_kernel,
                         cudaFuncAttributeMaxDynamicSharedMemorySize,
                         LSTM_SMEM_BYTES);
    lstm_kernel<<<NSEQ / SEQ_PER_BLOCK, LSTM_THREADS, LSTM_SMEM_BYTES>>>(
        U1, b1, W2, U2, b2);

    heads_kernel<<<912, 128>>>(
        (const float*)d_in[10], (const float*)d_in[11], (const float*)d_in[12],
        (const float*)d_in[13], (const float*)d_in[14], (const float*)d_in[15],
        (const float*)d_in[16], (const float*)d_in[17], (const float*)d_in[18],
        (const float*)d_in[19], (const float*)d_in[20], (const float*)d_in[21],
        (const float*)d_in[22], (const float*)d_in[23], (const float*)d_in[24],
        (const float*)d_in[25], (const float*)d_in[26], (const float*)d_in[27],
        out);
}

// round 12
// speedup vs baseline: 1.7054x; 1.0226x over previous
#include <cuda_runtime.h>
#include <cuda_bf16.h>
#include <mma.h>
#include <cstdint>

using namespace nvcuda;

// ---------------- problem constants ----------------
#define T_LEN   128
#define E_DIM   768
#define H1      128
#define H2      64
#define G1      512   // 4*H1
#define G2      256   // 4*H2
#define NSEQ    920
#define MROWS   (NSEQ * T_LEN)   // 117760
#define SEQ_PER_BLOCK 8
#define LSTM_THREADS  512

#define ROW_SUP_END 25600
#define ROW_QRY_END 51200
#define ROW_UNL_END 116736

// ---------------- scratch ----------------
__device__ float g_xw1[(long)MROWS * G1];   // 241 MB
__device__ float g_enc[NSEQ * H2];

// ---------------- helpers ----------------
typedef unsigned long long u64t;

__device__ __forceinline__ float tanh_ap(float x) {
    float y; asm("tanh.approx.f32 %0, %1;" : "=f"(y) : "f"(x)); return y;
}
__device__ __forceinline__ float fsig(float x) {
    return fmaf(tanh_ap(0.5f * x), 0.5f, 0.5f);
}
__device__ __forceinline__ u64t ffma2p(u64t a, u64t b, u64t c) {
    u64t d;
    asm("fma.rn.f32x2 %0, %1, %2, %3;" : "=l"(d) : "l"(a), "l"(b), "l"(c));
    return d;
}
__device__ __forceinline__ u64t pack2(float x, float y) {
    u64t d; asm("mov.b64 %0, {%1, %2};" : "=l"(d) : "f"(x), "f"(y)); return d;
}
__device__ __forceinline__ void unpack2(u64t v, float& x, float& y) {
    asm("mov.b64 {%0, %1}, %2;" : "=f"(x), "=f"(y) : "l"(v));
}
__device__ __forceinline__ void cp16(void* smemDst, const void* gmemSrc) {
    unsigned sa = (unsigned)__cvta_generic_to_shared(smemDst);
    asm volatile("cp.async.cg.shared.global [%0], [%1], 16;\n" :: "r"(sa), "l"(gmemSrc));
}
#define CP_COMMIT() asm volatile("cp.async.commit_group;\n" ::)

// =====================================================================
// Kernel 1: xw1 = X @ W1 (unchanged from R11 best)
// =====================================================================
#define BM 128
#define BN 128
#define BK 32
#define ASTRIDE 40
#define BSTRIDE 136
#define STAGE_FLOATS (BM*ASTRIDE + BK*BSTRIDE)           // 9472
#define GEMM_SMEM_FLOATS (3 * STAGE_FLOATS)              // 28416
#define GEMM_SMEM_BYTES  (GEMM_SMEM_FLOATS * 4)          // 113664

__global__ __launch_bounds__(256, 2) void gemm1_kernel(
    const float* __restrict__ support,
    const float* __restrict__ query,
    const float* __restrict__ unlabel,
    const float* __restrict__ model,
    const float* __restrict__ W1)
{
    extern __shared__ float gsm[];

    const int bn = blockIdx.x;
    const int bm = blockIdx.y;
    const long row0 = (long)bm * BM;

    const float* A;
    long arow;
    if (row0 < ROW_SUP_END)      { A = support; arow = row0; }
    else if (row0 < ROW_QRY_END) { A = query;   arow = row0 - ROW_SUP_END; }
    else if (row0 < ROW_UNL_END) { A = unlabel; arow = row0 - ROW_QRY_END; }
    else                         { A = model;   arow = row0 - ROW_UNL_END; }
    const float* Abase = A + arow * E_DIM;

    const int tid  = threadIdx.x;
    const int warp = tid >> 5;
    const int wm   = warp & 3;
    const int wn   = warp >> 2;

    wmma::fragment<wmma::accumulator, 16, 16, 8, float> cf[2][4];
    #pragma unroll
    for (int i = 0; i < 2; i++)
        #pragma unroll
        for (int jj = 0; jj < 4; jj++)
            wmma::fill_fragment(cf[i][jj], 0.0f);

    auto load_stage = [&](int st, int k0) {
        float* Ad = gsm + st * STAGE_FLOATS;
        float* Bd = Ad + BM * ASTRIDE;
        #pragma unroll
        for (int i = 0; i < 4; i++) {
            int idx = tid + i * 256;
            int r = idx >> 3, c = (idx & 7) * 4;
            cp16(&Ad[r * ASTRIDE + c], Abase + (long)r * E_DIM + k0 + c);
        }
        #pragma unroll
        for (int i = 0; i < 4; i++) {
            int idx = tid + i * 256;
            int r = idx >> 5, c = (idx & 31) * 4;
            cp16(&Bd[r * BSTRIDE + c], W1 + (long)(k0 + r) * G1 + bn * BN + c);
        }
        CP_COMMIT();
    };

    load_stage(0, 0);
    load_stage(1, BK);

    const int NKT = E_DIM / BK;
    int st = 0;
    for (int kt = 0; kt < NKT; kt++) {
        if (kt < NKT - 1) asm volatile("cp.async.wait_group 1;\n" ::);
        else              asm volatile("cp.async.wait_group 0;\n" ::);
        __syncthreads();

        if (kt + 2 < NKT) {
            int st2 = st + 2; if (st2 >= 3) st2 -= 3;
            load_stage(st2, (kt + 2) * BK);
        }

        const float* Ac = gsm + st * STAGE_FLOATS;
        const float* Bc = Ac + BM * ASTRIDE;
        #pragma unroll
        for (int kk = 0; kk < 4; kk++) {
            wmma::fragment<wmma::matrix_a, 16, 16, 8, wmma::precision::tf32, wmma::row_major> af[2];
            #pragma unroll
            for (int i = 0; i < 2; i++)
                wmma::load_matrix_sync(af[i], &Ac[(wm * 32 + i * 16) * ASTRIDE + kk * 8], ASTRIDE);
            #pragma unroll
            for (int jj = 0; jj < 4; jj++) {
                wmma::fragment<wmma::matrix_b, 16, 16, 8, wmma::precision::tf32, wmma::row_major> bf;
                wmma::load_matrix_sync(bf, &Bc[(kk * 8) * BSTRIDE + wn * 64 + jj * 16], BSTRIDE);
                #pragma unroll
                for (int i = 0; i < 2; i++)
                    wmma::mma_sync(cf[i][jj], af[i], bf, cf[i][jj]);
            }
        }
        if (++st >= 3) st -= 3;
    }

    #pragma unroll
    for (int i = 0; i < 2; i++)
        #pragma unroll
        for (int jj = 0; jj < 4; jj++) {
            float* dst = &g_xw1[(row0 + wm * 32 + i * 16) * (long)G1 + bn * BN + wn * 64 + jj * 16];
            wmma::store_matrix_sync(dst, cf[i][jj], G1, wmma::mem_row_major);
        }
}

// =====================================================================
// Kernel 2: fused LSTM1+LSTM2, MERGED PHASES:
// each iteration computes z2(t) AND z1(t+1) (both depend only on h1(t),
// h2(t-1)) in one phase -> 2 syncs/step instead of 4, bigger independent
// issue windows (Phase-B smem work hides Phase-A L2/DRAM latency).
// smem (floats):
//   sW2   [0,     32768)   128x256
//   sU2   [32768, 49152)   64x256
//   zbufA [49152, 53248)   8x512
//   zbufB [53248, 55296)   8x256
//   h1T   [55296, 56320)   [k=128][s=8]
//   h2T   [56320, 56832)   [k=64][s=8]
// total 56832 floats = 227328 bytes
// =====================================================================
#define LSTM_SMEM_FLOATS 56832
#define LSTM_SMEM_BYTES  (LSTM_SMEM_FLOATS * 4)

__global__ __launch_bounds__(LSTM_THREADS) void lstm_kernel(
    const float* __restrict__ U1,
    const float* __restrict__ b1,
    const float* __restrict__ W2,
    const float* __restrict__ U2,
    const float* __restrict__ b2)
{
    extern __shared__ float sm[];
    float* sW2   = sm;
    float* sU2   = sm + 32768;
    float* zbufA = sm + 49152;
    float* zbufB = sm + 53248;
    float* h1T   = sm + 55296;
    float* h2T   = sm + 56320;

    const int tid = threadIdx.x;
    const long qbase = (long)blockIdx.x * SEQ_PER_BLOCK;

    {
        const float4* s4 = (const float4*)W2;
        float4* d4 = (float4*)sW2;
        for (int i = tid; i < (H1 * G2) / 4; i += LSTM_THREADS) d4[i] = s4[i];
        s4 = (const float4*)U2; d4 = (float4*)sU2;
        for (int i = tid; i < (H2 * G2) / 4; i += LSTM_THREADS) d4[i] = s4[i];
        if (tid < 64 * 8) h2T[tid] = 0.0f;
    }

    float c1a = 0.0f, c1b = 0.0f, c2 = 0.0f;

    const int j  = tid;               // Phase A gate col
    const int j2 = tid & 255;         // Phase B gate col
    const int s0 = (tid >> 8) * 4;    // Phase B seq group

    const int p0s = tid >> 7, p0n = tid & 127;
    const int p1s = 4 + (tid >> 7), p1n = tid & 127;
    const int u2s = tid >> 6, u2n = tid & 63;

    const float* xp0 = g_xw1 + (qbase * T_LEN) * (long)G1 + j;
    const float* U1j = U1 + j;
    const float  bb  = b1[j];
    const float  b2v = b2[j2];
    const u64t   b2p = pack2(b2v, b2v);

    __syncthreads();   // weights + h2T init visible

    // ---- prologue: z1(0) = xw(0) + b1   (h1(-1) = 0) ----
    {
        #pragma unroll
        for (int s = 0; s < 8; s++)
            zbufA[s * G1 + j] = xp0[(long)s * T_LEN * G1] + bb;
    }
    __syncthreads();
    // update1(0) -> h1(0)
    {
        const float* zb = &zbufA[p0s * G1];
        float zi = zb[p0n], zf = zb[128 + p0n], zg = zb[256 + p0n], zo = zb[384 + p0n];
        c1a = fsig(zf) * c1a + fsig(zi) * tanh_ap(zg);
        h1T[p0n * 8 + p0s] = fsig(zo) * tanh_ap(c1a);
    }
    {
        const float* zb = &zbufA[p1s * G1];
        float zi = zb[p1n], zf = zb[128 + p1n], zg = zb[256 + p1n], zo = zb[384 + p1n];
        c1b = fsig(zf) * c1b + fsig(zi) * tanh_ap(zg);
        h1T[p1n * 8 + p1s] = fsig(zo) * tanh_ap(c1b);
    }
    __syncthreads();

    for (int t = 0; t < T_LEN; t++) {
        const bool notlast = (t < T_LEN - 1);

        // xw1 loads for t+1 (DRAM; issued first, consumed last)
        float xv[8];
        if (notlast) {
            const float* xp = xp0 + (long)(t + 1) * G1;
            #pragma unroll
            for (int s = 0; s < 8; s++) xv[s] = xp[(long)s * T_LEN * G1];
        }

        // ---- matvec B: z2(t) = b2 + h1(t)@W2 + h2(t-1)@U2 ----
        u64t a2a = b2p, a2b = b2p;
        #pragma unroll 8
        for (int k = 0; k < H1; k++) {
            ulonglong2 hv = *(const ulonglong2*)&h1T[k * 8 + s0];
            float wv = sW2[k * G2 + j2];
            u64t ww = pack2(wv, wv);
            a2a = ffma2p(hv.x, ww, a2a);
            a2b = ffma2p(hv.y, ww, a2b);
        }
        #pragma unroll 8
        for (int k = 0; k < H2; k++) {
            ulonglong2 hv = *(const ulonglong2*)&h2T[k * 8 + s0];
            float uv = sU2[k * G2 + j2];
            u64t uu = pack2(uv, uv);
            a2a = ffma2p(hv.x, uu, a2a);
            a2b = ffma2p(hv.y, uu, a2b);
        }

        // ---- matvec A: z1(t+1) = h1(t)@U1 (+ xw + b later) ----
        u64t a01 = 0ull, a23 = 0ull, a45 = 0ull, a67 = 0ull;
        if (notlast) {
            #pragma unroll 1
            for (int kb = 0; kb < H1; kb += 16) {
                float u[16];
                #pragma unroll
                for (int i = 0; i < 16; i++) u[i] = U1j[(kb + i) * G1];
                #pragma unroll
                for (int i = 0; i < 16; i++) {
                    ulonglong2 hA = *(const ulonglong2*)&h1T[(kb + i) * 8];
                    ulonglong2 hB = *(const ulonglong2*)&h1T[(kb + i) * 8 + 4];
                    u64t uu = pack2(u[i], u[i]);
                    a01 = ffma2p(hA.x, uu, a01);
                    a23 = ffma2p(hA.y, uu, a23);
                    a45 = ffma2p(hB.x, uu, a45);
                    a67 = ffma2p(hB.y, uu, a67);
                }
            }
        }

        // ---- stores ----
        {
            float y0, y1, y2, y3;
            unpack2(a2a, y0, y1); unpack2(a2b, y2, y3);
            zbufB[(s0 + 0) * G2 + j2] = y0;
            zbufB[(s0 + 1) * G2 + j2] = y1;
            zbufB[(s0 + 2) * G2 + j2] = y2;
            zbufB[(s0 + 3) * G2 + j2] = y3;
        }
        if (notlast) {
            float z0, z1, z2, z3, z4, z5, z6, z7;
            unpack2(a01, z0, z1); unpack2(a23, z2, z3);
            unpack2(a45, z4, z5); unpack2(a67, z6, z7);
            zbufA[0 * G1 + j] = z0 + xv[0] + bb;
            zbufA[1 * G1 + j] = z1 + xv[1] + bb;
            zbufA[2 * G1 + j] = z2 + xv[2] + bb;
            zbufA[3 * G1 + j] = z3 + xv[3] + bb;
            zbufA[4 * G1 + j] = z4 + xv[4] + bb;
            zbufA[5 * G1 + j] = z5 + xv[5] + bb;
            zbufA[6 * G1 + j] = z6 + xv[6] + bb;
            zbufA[7 * G1 + j] = z7 + xv[7] + bb;
        }
        __syncthreads();

        // ---- update2(t): h2(t), c2 ----
        {
            const float* zb = &zbufB[u2s * G2];
            float zi = zb[u2n], zf = zb[64 + u2n], zg = zb[128 + u2n], zo = zb[192 + u2n];
            c2 = fsig(zf) * c2 + fsig(zi) * tanh_ap(zg);
            h2T[u2n * 8 + u2s] = fsig(zo) * tanh_ap(c2);
        }
        // ---- update1(t+1): h1(t+1), c1 ----
        if (notlast) {
            {
                const float* zb = &zbufA[p0s * G1];
                float zi = zb[p0n], zf = zb[128 + p0n], zg = zb[256 + p0n], zo = zb[384 + p0n];
                c1a = fsig(zf) * c1a + fsig(zi) * tanh_ap(zg);
                h1T[p0n * 8 + p0s] = fsig(zo) * tanh_ap(c1a);
            }
            {
                const float* zb = &zbufA[p1s * G1];
                float zi = zb[p1n], zf = zb[128 + p1n], zg = zb[256 + p1n], zo = zb[384 + p1n];
                c1b = fsig(zf) * c1b + fsig(zi) * tanh_ap(zg);
                h1T[p1n * 8 + p1s] = fsig(zo) * tanh_ap(c1b);
            }
        }
        __syncthreads();
    }

    g_enc[(qbase + u2s) * H2 + u2n] = h2T[u2n * 8 + u2s];
}

// =====================================================================
// Kernel 3: ALL heads in one launch (unchanged)
// =====================================================================
__global__ __launch_bounds__(128) void heads_kernel(
    const float* __restrict__ W1h, const float* __restrict__ b1h,
    const float* __restrict__ g1h, const float* __restrict__ be1,
    const float* __restrict__ m1h, const float* __restrict__ v1h,
    const float* __restrict__ W2h, const float* __restrict__ b2h,
    const float* __restrict__ g2h, const float* __restrict__ be2,
    const float* __restrict__ m2h, const float* __restrict__ v2h,
    const float* __restrict__ W3h, const float* __restrict__ b3h,
    const float* __restrict__ g3h, const float* __restrict__ be3,
    const float* __restrict__ m3h, const float* __restrict__ v3h,
    float* __restrict__ out)
{
    __shared__ float x[128];
    const int row = blockIdx.x;
    const int tid = threadIdx.x;

    const float *W, *b, *g, *beta, *m, *v;
    int bidx;
    if (row < 200)      { W = W1h; b = b1h; g = g1h; beta = be1; m = m1h; v = v1h; bidx = row / 25; }
    else if (row < 400) { W = W2h; b = b2h; g = g2h; beta = be2; m = m2h; v = v2h; bidx = (row - 200) / 25; }
    else                { W = W3h; b = b3h; g = g3h; beta = be3; m = m3h; v = v3h; bidx = (row - 400) / 64; }

    if (tid < 64) x[tid] = g_enc[row * H2 + tid];
    else          x[tid] = g_enc[(912 + bidx) * H2 + (tid - 64)];
    __syncthreads();

    if (tid < 32) {
        float acc = b[tid];
        #pragma unroll 8
        for (int k = 0; k < 128; k++) acc = fmaf(x[k], W[k * 32 + tid], acc);
        float y = fmaxf(acc, 0.0f);
        out[row * 32 + tid] = g[tid] * (y - m[tid]) * rsqrtf(v[tid] + 1e-3f) + beta[tid];
    }
}

// =====================================================================
extern "C" void kernel_launch(void* const* d_in, const int* in_sizes, int n_in,
                              void* d_out, int out_size)
{
    (void)in_sizes; (void)n_in; (void)out_size;

    const float* support = (const float*)d_in[0];
    const float* query   = (const float*)d_in[1];
    const float* unlabel = (const float*)d_in[2];
    const float* model   = (const float*)d_in[3];
    const float* W1 = (const float*)d_in[4];
    const float* U1 = (const float*)d_in[5];
    const float* b1 = (const float*)d_in[6];
    const float* W2 = (const float*)d_in[7];
    const float* U2 = (const float*)d_in[8];
    const float* b2 = (const float*)d_in[9];
    float* out = (float*)d_out;

    cudaFuncSetAttribute(gemm1_kernel,
                         cudaFuncAttributeMaxDynamicSharedMemorySize,
                         GEMM_SMEM_BYTES);
    dim3 ggrid(G1 / BN, MROWS / BM);   // (4, 920)
    gemm1_kernel<<<ggrid, 256, GEMM_SMEM_BYTES>>>(support, query, unlabel, model, W1);

    cudaFuncSetAttribute(lstm_kernel,
                         cudaFuncAttributeMaxDynamicSharedMemorySize,
                         LSTM_SMEM_BYTES);
    lstm_kernel<<<NSEQ / SEQ_PER_BLOCK, LSTM_THREADS, LSTM_SMEM_BYTES>>>(
        U1, b1, W2, U2, b2);

    heads_kernel<<<912, 128>>>(
        (const float*)d_in[10], (const float*)d_in[11], (const float*)d_in[12],
        (const float*)d_in[13], (const float*)d_in[14], (const float*)d_in[15],
        (const float*)d_in[16], (const float*)d_in[17], (const float*)d_in[18],
        (const float*)d_in[19], (const float*)d_in[20], (const float*)d_in[21],
        (const float*)d_in[22], (const float*)d_in[23], (const float*)d_in[24],
        (const float*)d_in[25], (const float*)d_in[26], (const float*)d_in[27],
        out);
}